// round 1
// baseline (speedup 1.0000x reference)
#include <cuda_runtime.h>
#include <cstdint>

#define N_TOK 8192
#define D_DIM 4096
#define E_EXP 8
#define R_RANK 16
#define EJ (E_EXP * R_RANK)   // 128
#define SCALING_F 2.0f

// Scratch (device globals — no allocation allowed)
__device__ float g_wfull[N_TOK * E_EXP];   // routing weight * SCALING, dense [N,E]
__device__ float g_t[N_TOK * EJ];          // t[n, e*16+r] = w*SCALING*(x·A[e,r])

// ---------------- packed f32x2 helpers (full-rate FMA on sm_103a) -------------
__device__ __forceinline__ unsigned long long dup2(float a) {
    unsigned long long r;
    asm("mov.b64 %0, {%1, %1};" : "=l"(r) : "f"(a));
    return r;
}
__device__ __forceinline__ void ffma2(unsigned long long& c, unsigned long long a,
                                      unsigned long long b) {
    asm("fma.rn.f32x2 %0, %1, %2, %3;" : "=l"(c) : "l"(a), "l"(b), "l"(c));
}
__device__ __forceinline__ float2 unpk(unsigned long long v) {
    float2 r;
    asm("mov.b64 {%0, %1}, %2;" : "=f"(r.x), "=f"(r.y) : "l"(v));
    return r;
}

// ---------------- Kernel 1: gate logits + top-k softmax ----------------------
// One warp per token; gate_W staged through smem in 8x512 chunks.
__global__ __launch_bounds__(128) void gate_kernel(const float* __restrict__ x,
                                                   const float* __restrict__ gw,
                                                   const int* __restrict__ topk_p) {
    __shared__ float sgw[E_EXP][512];
    const int warp = threadIdx.x >> 5, lane = threadIdx.x & 31;
    const int n = blockIdx.x * 4 + warp;

    float acc[E_EXP];
#pragma unroll
    for (int e = 0; e < E_EXP; e++) acc[e] = 0.f;

    for (int kt = 0; kt < D_DIM / 512; kt++) {
        __syncthreads();
        // load 8x512 chunk: 1024 float4s, 128 threads -> 8 each
        for (int i = threadIdx.x; i < E_EXP * 128; i += blockDim.x) {
            int e = i >> 7, kv = i & 127;
            ((float4*)sgw[e])[kv] =
                ((const float4*)(gw + e * D_DIM + kt * 512))[kv];
        }
        __syncthreads();
        const float4* xr = (const float4*)(x + (size_t)n * D_DIM + kt * 512);
#pragma unroll 4
        for (int k4 = lane; k4 < 128; k4 += 32) {
            float4 xv = xr[k4];
#pragma unroll
            for (int e = 0; e < E_EXP; e++) {
                float4 wv = ((float4*)sgw[e])[k4];
                acc[e] += xv.x * wv.x + xv.y * wv.y + xv.z * wv.z + xv.w * wv.w;
            }
        }
    }
#pragma unroll
    for (int e = 0; e < E_EXP; e++)
#pragma unroll
        for (int off = 16; off; off >>= 1)
            acc[e] += __shfl_xor_sync(0xffffffffu, acc[e], off);

    if (lane == 0) {
        const int K = *topk_p;
        bool sel[E_EXP];
        int idxs[E_EXP];
#pragma unroll
        for (int e = 0; e < E_EXP; e++) sel[e] = false;
        for (int t = 0; t < K; t++) {
            int best = 0;
            float bv = -3.0e38f;
            for (int e = 0; e < E_EXP; e++)
                if (!sel[e] && acc[e] > bv) { bv = acc[e]; best = e; }
            sel[best] = true;
            idxs[t] = best;
        }
        float mx = acc[idxs[0]];
        for (int t = 1; t < K; t++) mx = fmaxf(mx, acc[idxs[t]]);
        float p[E_EXP], s = 0.f;
        for (int t = 0; t < K; t++) { p[t] = expf(acc[idxs[t]] - mx); s += p[t]; }
        float inv = 1.0f / s;
        for (int e = 0; e < E_EXP; e++) g_wfull[n * E_EXP + e] = 0.f;
        for (int t = 0; t < K; t++)
            g_wfull[n * E_EXP + idxs[t]] = SCALING_F * p[t] * inv;
    }
}

// ---------------- Kernel 2: t = (x @ A^T) * w_full ---------------------------
// GEMM [8192,4096] x [4096,128]. BM=64, BN=128, BK=16, 256 thr, 4x8 per thread.
__global__ __launch_bounds__(256) void t_kernel(const float* __restrict__ x,
                                                const float* __restrict__ A) {
    __shared__ float xs[2][16][68];
    __shared__ float as[2][16][132];
    const int tx = threadIdx.x & 15, ty = threadIdx.x >> 4;
    const int bm = blockIdx.x * 64;

    const int lrow = threadIdx.x >> 2;       // 0..63
    const int lkv = (threadIdx.x & 3) * 4;   // 0,4,8,12
    const float* xg = x + (size_t)(bm + lrow) * D_DIM + lkv;
    const float* ag0 = A + (size_t)lrow * D_DIM + lkv;
    const float* ag1 = A + (size_t)(lrow + 64) * D_DIM + lkv;

    float acc[4][8];
#pragma unroll
    for (int i = 0; i < 4; i++)
#pragma unroll
        for (int j = 0; j < 8; j++) acc[i][j] = 0.f;

    float4 xv, av0, av1;
    // prologue: tile 0
    xv = *(const float4*)(xg);
    av0 = *(const float4*)(ag0);
    av1 = *(const float4*)(ag1);
    {
        xs[0][lkv + 0][lrow] = xv.x; xs[0][lkv + 1][lrow] = xv.y;
        xs[0][lkv + 2][lrow] = xv.z; xs[0][lkv + 3][lrow] = xv.w;
        as[0][lkv + 0][lrow] = av0.x; as[0][lkv + 1][lrow] = av0.y;
        as[0][lkv + 2][lrow] = av0.z; as[0][lkv + 3][lrow] = av0.w;
        as[0][lkv + 0][lrow + 64] = av1.x; as[0][lkv + 1][lrow + 64] = av1.y;
        as[0][lkv + 2][lrow + 64] = av1.z; as[0][lkv + 3][lrow + 64] = av1.w;
    }
    __syncthreads();

    const int NKT = D_DIM / 16;
    for (int kt = 0; kt < NKT; kt++) {
        int buf = kt & 1;
        if (kt + 1 < NKT) {
            xv = *(const float4*)(xg + (kt + 1) * 16);
            av0 = *(const float4*)(ag0 + (kt + 1) * 16);
            av1 = *(const float4*)(ag1 + (kt + 1) * 16);
        }
#pragma unroll
        for (int kk = 0; kk < 16; kk++) {
            float4 a_ = *(const float4*)&xs[buf][kk][ty * 4];
            float4 b0 = *(const float4*)&as[buf][kk][tx * 8];
            float4 b1 = *(const float4*)&as[buf][kk][tx * 8 + 4];
            float bb[8] = {b0.x, b0.y, b0.z, b0.w, b1.x, b1.y, b1.z, b1.w};
            float aa[4] = {a_.x, a_.y, a_.z, a_.w};
#pragma unroll
            for (int i = 0; i < 4; i++)
#pragma unroll
                for (int j = 0; j < 8; j++) acc[i][j] = fmaf(aa[i], bb[j], acc[i][j]);
        }
        if (kt + 1 < NKT) {
            int nb = buf ^ 1;
            xs[nb][lkv + 0][lrow] = xv.x; xs[nb][lkv + 1][lrow] = xv.y;
            xs[nb][lkv + 2][lrow] = xv.z; xs[nb][lkv + 3][lrow] = xv.w;
            as[nb][lkv + 0][lrow] = av0.x; as[nb][lkv + 1][lrow] = av0.y;
            as[nb][lkv + 2][lrow] = av0.z; as[nb][lkv + 3][lrow] = av0.w;
            as[nb][lkv + 0][lrow + 64] = av1.x; as[nb][lkv + 1][lrow + 64] = av1.y;
            as[nb][lkv + 2][lrow + 64] = av1.z; as[nb][lkv + 3][lrow + 64] = av1.w;
        }
        __syncthreads();
    }

    // epilogue: scale by routing weight (expert = tx>>1 covers this thread's 8 cols)
    const int e = tx >> 1;
#pragma unroll
    for (int i = 0; i < 4; i++) {
        int n_ = bm + ty * 4 + i;
        float w = g_wfull[n_ * E_EXP + e];
        float4 o0 = make_float4(acc[i][0] * w, acc[i][1] * w, acc[i][2] * w, acc[i][3] * w);
        float4 o1 = make_float4(acc[i][4] * w, acc[i][5] * w, acc[i][6] * w, acc[i][7] * w);
        *(float4*)&g_t[(size_t)n_ * EJ + tx * 8] = o0;
        *(float4*)&g_t[(size_t)n_ * EJ + tx * 8 + 4] = o1;
    }
}

// ---------------- Kernel 3: y = x @ W^T  (+ t @ Bcat^T epilogue) -------------
// BM=BN=128, BK=16, 256 threads, 8x8 per thread, f32x2 packed accumulators,
// double-buffered smem with register staging (global->reg->smem transposed).
__global__ __launch_bounds__(256) void main_kernel(const float* __restrict__ x,
                                                   const float* __restrict__ W,
                                                   const float* __restrict__ Bm,
                                                   float* __restrict__ y) {
    __shared__ float xs[2][16][132];
    __shared__ float ws[2][16][132];
    const int tx = threadIdx.x & 15, ty = threadIdx.x >> 4;
    const int bm = blockIdx.y * 128, bn = blockIdx.x * 128;

    unsigned long long acc[8][4];
#pragma unroll
    for (int m = 0; m < 8; m++)
#pragma unroll
        for (int p = 0; p < 4; p++) acc[m][p] = 0ull;

    const int lrow = threadIdx.x >> 2;       // 0..63 (handles lrow and lrow+64)
    const int lkv = (threadIdx.x & 3) * 4;   // 0,4,8,12
    const float* xg0 = x + (size_t)(bm + lrow) * D_DIM + lkv;
    const float* xg1 = x + (size_t)(bm + lrow + 64) * D_DIM + lkv;
    const float* wg0 = W + (size_t)(bn + lrow) * D_DIM + lkv;
    const float* wg1 = W + (size_t)(bn + lrow + 64) * D_DIM + lkv;

    float4 xv0, xv1, wv0, wv1;

    // prologue
    xv0 = *(const float4*)(xg0);
    xv1 = *(const float4*)(xg1);
    wv0 = *(const float4*)(wg0);
    wv1 = *(const float4*)(wg1);
    {
        xs[0][lkv + 0][lrow] = xv0.x; xs[0][lkv + 1][lrow] = xv0.y;
        xs[0][lkv + 2][lrow] = xv0.z; xs[0][lkv + 3][lrow] = xv0.w;
        xs[0][lkv + 0][lrow + 64] = xv1.x; xs[0][lkv + 1][lrow + 64] = xv1.y;
        xs[0][lkv + 2][lrow + 64] = xv1.z; xs[0][lkv + 3][lrow + 64] = xv1.w;
        ws[0][lkv + 0][lrow] = wv0.x; ws[0][lkv + 1][lrow] = wv0.y;
        ws[0][lkv + 2][lrow] = wv0.z; ws[0][lkv + 3][lrow] = wv0.w;
        ws[0][lkv + 0][lrow + 64] = wv1.x; ws[0][lkv + 1][lrow + 64] = wv1.y;
        ws[0][lkv + 2][lrow + 64] = wv1.z; ws[0][lkv + 3][lrow + 64] = wv1.w;
    }
    __syncthreads();

    const int NKT = D_DIM / 16;  // 256
    for (int kt = 0; kt < NKT; kt++) {
        const int buf = kt & 1;
        if (kt + 1 < NKT) {
            xv0 = *(const float4*)(xg0 + (kt + 1) * 16);
            xv1 = *(const float4*)(xg1 + (kt + 1) * 16);
            wv0 = *(const float4*)(wg0 + (kt + 1) * 16);
            wv1 = *(const float4*)(wg1 + (kt + 1) * 16);
        }
#pragma unroll
        for (int kk = 0; kk < 16; kk++) {
            float4 a0 = *(const float4*)&xs[buf][kk][ty * 8];
            float4 a1 = *(const float4*)&xs[buf][kk][ty * 8 + 4];
            const unsigned long long* bp =
                (const unsigned long long*)&ws[buf][kk][tx * 8];
            unsigned long long b0 = bp[0], b1 = bp[1], b2 = bp[2], b3 = bp[3];
            unsigned long long ad[8] = {dup2(a0.x), dup2(a0.y), dup2(a0.z), dup2(a0.w),
                                        dup2(a1.x), dup2(a1.y), dup2(a1.z), dup2(a1.w)};
#pragma unroll
            for (int m = 0; m < 8; m++) {
                ffma2(acc[m][0], ad[m], b0);
                ffma2(acc[m][1], ad[m], b1);
                ffma2(acc[m][2], ad[m], b2);
                ffma2(acc[m][3], ad[m], b3);
            }
        }
        if (kt + 1 < NKT) {
            const int nb = buf ^ 1;
            xs[nb][lkv + 0][lrow] = xv0.x; xs[nb][lkv + 1][lrow] = xv0.y;
            xs[nb][lkv + 2][lrow] = xv0.z; xs[nb][lkv + 3][lrow] = xv0.w;
            xs[nb][lkv + 0][lrow + 64] = xv1.x; xs[nb][lkv + 1][lrow + 64] = xv1.y;
            xs[nb][lkv + 2][lrow + 64] = xv1.z; xs[nb][lkv + 3][lrow + 64] = xv1.w;
            ws[nb][lkv + 0][lrow] = wv0.x; ws[nb][lkv + 1][lrow] = wv0.y;
            ws[nb][lkv + 2][lrow] = wv0.z; ws[nb][lkv + 3][lrow] = wv0.w;
            ws[nb][lkv + 0][lrow + 64] = wv1.x; ws[nb][lkv + 1][lrow + 64] = wv1.y;
            ws[nb][lkv + 2][lrow + 64] = wv1.z; ws[nb][lkv + 3][lrow + 64] = wv1.w;
        }
        __syncthreads();
    }

    // ---- LoRA epilogue: y += t @ Bcat^T  (K=128, 8 tiles of 16) ----
    // Bcat(j, d) = Bm[e*D*R + d*R + r], j = e*16+r; tile jt spans exactly e=jt.
    const float* tg0 = g_t + (size_t)(bm + lrow) * EJ + lkv;
    const float* tg1 = g_t + (size_t)(bm + lrow + 64) * EJ + lkv;
    const float* bg0 = Bm + (size_t)(bn + lrow) * R_RANK + lkv;
    const float* bg1 = Bm + (size_t)(bn + lrow + 64) * R_RANK + lkv;

    for (int jt = 0; jt < EJ / 16; jt++) {
        float4 tv0 = *(const float4*)(tg0 + jt * 16);
        float4 tv1 = *(const float4*)(tg1 + jt * 16);
        float4 bv0 = *(const float4*)(bg0 + (size_t)jt * D_DIM * R_RANK);
        float4 bv1 = *(const float4*)(bg1 + (size_t)jt * D_DIM * R_RANK);
        __syncthreads();  // previous tile's compute done before overwrite
        xs[0][lkv + 0][lrow] = tv0.x; xs[0][lkv + 1][lrow] = tv0.y;
        xs[0][lkv + 2][lrow] = tv0.z; xs[0][lkv + 3][lrow] = tv0.w;
        xs[0][lkv + 0][lrow + 64] = tv1.x; xs[0][lkv + 1][lrow + 64] = tv1.y;
        xs[0][lkv + 2][lrow + 64] = tv1.z; xs[0][lkv + 3][lrow + 64] = tv1.w;
        ws[0][lkv + 0][lrow] = bv0.x; ws[0][lkv + 1][lrow] = bv0.y;
        ws[0][lkv + 2][lrow] = bv0.z; ws[0][lkv + 3][lrow] = bv0.w;
        ws[0][lkv + 0][lrow + 64] = bv1.x; ws[0][lkv + 1][lrow + 64] = bv1.y;
        ws[0][lkv + 2][lrow + 64] = bv1.z; ws[0][lkv + 3][lrow + 64] = bv1.w;
        __syncthreads();
#pragma unroll
        for (int kk = 0; kk < 16; kk++) {
            float4 a0 = *(const float4*)&xs[0][kk][ty * 8];
            float4 a1 = *(const float4*)&xs[0][kk][ty * 8 + 4];
            const unsigned long long* bp =
                (const unsigned long long*)&ws[0][kk][tx * 8];
            unsigned long long b0 = bp[0], b1 = bp[1], b2 = bp[2], b3 = bp[3];
            unsigned long long ad[8] = {dup2(a0.x), dup2(a0.y), dup2(a0.z), dup2(a0.w),
                                        dup2(a1.x), dup2(a1.y), dup2(a1.z), dup2(a1.w)};
#pragma unroll
            for (int m = 0; m < 8; m++) {
                ffma2(acc[m][0], ad[m], b0);
                ffma2(acc[m][1], ad[m], b1);
                ffma2(acc[m][2], ad[m], b2);
                ffma2(acc[m][3], ad[m], b3);
            }
        }
    }

    // ---- write out ----
#pragma unroll
    for (int m = 0; m < 8; m++) {
        float2 c01 = unpk(acc[m][0]), c23 = unpk(acc[m][1]);
        float2 c45 = unpk(acc[m][2]), c67 = unpk(acc[m][3]);
        float* yr = y + (size_t)(bm + ty * 8 + m) * D_DIM + bn + tx * 8;
        *(float4*)yr = make_float4(c01.x, c01.y, c23.x, c23.y);
        *(float4*)(yr + 4) = make_float4(c45.x, c45.y, c67.x, c67.y);
    }
}

// -----------------------------------------------------------------------------
extern "C" void kernel_launch(void* const* d_in, const int* in_sizes, int n_in,
                              void* d_out, int out_size) {
    const float* x = (const float*)d_in[0];
    const float* base_W = (const float*)d_in[1];
    const float* gate_W = (const float*)d_in[2];
    const float* A = (const float*)d_in[3];
    const float* B = (const float*)d_in[4];
    const int* topk = (const int*)d_in[5];
    float* y = (float*)d_out;

    gate_kernel<<<N_TOK / 4, 128>>>(x, gate_W, topk);
    t_kernel<<<N_TOK / 64, 256>>>(x, A);
    main_kernel<<<dim3(D_DIM / 128, N_TOK / 128), 256>>>(x, base_W, B, y);
}

// round 4
// speedup vs baseline: 1.4857x; 1.4857x over previous
#include <cuda_runtime.h>
#include <cuda_bf16.h>
#include <cstdint>

#define N_TOK 8192
#define D_DIM 4096
#define E_EXP 8
#define R_RANK 16
#define EJ (E_EXP * R_RANK)   // 128
#define SCALING_F 2.0f

// ---------------- device-global scratch (no allocation allowed) --------------
__device__ float          g_wfull[N_TOK * E_EXP];
__device__ __nv_bfloat16  g_xhi[(size_t)N_TOK * D_DIM];
__device__ __nv_bfloat16  g_xlo[(size_t)N_TOK * D_DIM];
__device__ __nv_bfloat16  g_whi[(size_t)D_DIM * D_DIM];
__device__ __nv_bfloat16  g_wlo[(size_t)D_DIM * D_DIM];
__device__ __nv_bfloat16  g_tbf[(size_t)N_TOK * EJ];     // t in bf16 [8192][128]
__device__ __nv_bfloat16  g_bcatT[(size_t)D_DIM * EJ];   // BcatT[d][j=e*16+r]

// ---------------- helpers ----------------------------------------------------
__device__ __forceinline__ uint32_t smem_u32(const void* p) {
    uint32_t a;
    asm("{ .reg .u64 t; cvta.to.shared.u64 t, %1; cvt.u32.u64 %0, t; }" : "=r"(a) : "l"(p));
    return a;
}
__device__ __forceinline__ void cp16(uint32_t dst, const void* src) {
    asm volatile("cp.async.cg.shared.global [%0], [%1], 16;" :: "r"(dst), "l"(src));
}
__device__ __forceinline__ void cp_commit() {
    asm volatile("cp.async.commit_group;" ::: "memory");
}
__device__ __forceinline__ void cp_wait1() {
    asm volatile("cp.async.wait_group 1;" ::: "memory");
}
__device__ __forceinline__ void ldm4(uint32_t* r, uint32_t addr) {
    asm volatile("ldmatrix.sync.aligned.m8n8.x4.shared.b16 {%0,%1,%2,%3}, [%4];"
                 : "=r"(r[0]), "=r"(r[1]), "=r"(r[2]), "=r"(r[3]) : "r"(addr));
}
__device__ __forceinline__ void mma_bf16(float* c, const uint32_t* a, uint32_t b0,
                                         uint32_t b1) {
    asm volatile(
        "mma.sync.aligned.m16n8k16.row.col.f32.bf16.bf16.f32 "
        "{%0,%1,%2,%3}, {%4,%5,%6,%7}, {%8,%9}, {%0,%1,%2,%3};"
        : "+f"(c[0]), "+f"(c[1]), "+f"(c[2]), "+f"(c[3])
        : "r"(a[0]), "r"(a[1]), "r"(a[2]), "r"(a[3]), "r"(b0), "r"(b1));
}
__device__ __forceinline__ uint32_t pack_bf2(float a, float b) {
    __nv_bfloat162 t = __floats2bfloat162_rn(a, b);
    return *reinterpret_cast<uint32_t*>(&t);
}

// ---------------- conversion kernels -----------------------------------------
__device__ __forceinline__ void split_body(const float* __restrict__ src,
                                           __nv_bfloat16* __restrict__ hi,
                                           __nv_bfloat16* __restrict__ lo, int n4) {
    for (int i = blockIdx.x * blockDim.x + threadIdx.x; i < n4; i += gridDim.x * blockDim.x) {
        float4 v = ((const float4*)src)[i];
        __nv_bfloat16 h0 = __float2bfloat16_rn(v.x), h1 = __float2bfloat16_rn(v.y);
        __nv_bfloat16 h2 = __float2bfloat16_rn(v.z), h3 = __float2bfloat16_rn(v.w);
        float l0 = v.x - __bfloat162float(h0), l1 = v.y - __bfloat162float(h1);
        float l2 = v.z - __bfloat162float(h2), l3 = v.w - __bfloat162float(h3);
        uint2 ph, pl;
        {
            __nv_bfloat162 a = {h0, h1}, b = {h2, h3};
            ph.x = *reinterpret_cast<uint32_t*>(&a);
            ph.y = *reinterpret_cast<uint32_t*>(&b);
        }
        pl.x = pack_bf2(l0, l1);
        pl.y = pack_bf2(l2, l3);
        ((uint2*)hi)[i] = ph;
        ((uint2*)lo)[i] = pl;
    }
}
__global__ __launch_bounds__(256) void split_x_kernel(const float* __restrict__ x) {
    split_body(x, g_xhi, g_xlo, (N_TOK * D_DIM) / 4);
}
__global__ __launch_bounds__(256) void split_w_kernel(const float* __restrict__ w) {
    split_body(w, g_whi, g_wlo, (D_DIM * D_DIM) / 4);
}

__global__ __launch_bounds__(256) void bcat_kernel(const float* __restrict__ B) {
    int i = blockIdx.x * blockDim.x + threadIdx.x;  // 4096*128
    if (i >= D_DIM * EJ) return;
    int d = i >> 7, j = i & 127, e = j >> 4, r = j & 15;
    g_bcatT[(size_t)d * EJ + j] =
        __float2bfloat16_rn(B[(size_t)e * D_DIM * R_RANK + (size_t)d * R_RANK + r]);
}

// ---------------- gate: logits + top-k softmax -> g_wfull --------------------
__global__ __launch_bounds__(128) void gate_kernel(const float* __restrict__ x,
                                                   const float* __restrict__ gw,
                                                   const int* __restrict__ topk_p) {
    __shared__ float sgw[E_EXP][512];
    const int warp = threadIdx.x >> 5, lane = threadIdx.x & 31;
    const int n = blockIdx.x * 4 + warp;

    float acc[E_EXP];
#pragma unroll
    for (int e = 0; e < E_EXP; e++) acc[e] = 0.f;

    for (int kt = 0; kt < D_DIM / 512; kt++) {
        __syncthreads();
        for (int i = threadIdx.x; i < E_EXP * 128; i += blockDim.x) {
            int e = i >> 7, kv = i & 127;
            ((float4*)sgw[e])[kv] = ((const float4*)(gw + e * D_DIM + kt * 512))[kv];
        }
        __syncthreads();
        const float4* xr = (const float4*)(x + (size_t)n * D_DIM + kt * 512);
#pragma unroll 4
        for (int k4 = lane; k4 < 128; k4 += 32) {
            float4 xv = xr[k4];
#pragma unroll
            for (int e = 0; e < E_EXP; e++) {
                float4 wv = ((float4*)sgw[e])[k4];
                acc[e] += xv.x * wv.x + xv.y * wv.y + xv.z * wv.z + xv.w * wv.w;
            }
        }
    }
#pragma unroll
    for (int e = 0; e < E_EXP; e++)
#pragma unroll
        for (int off = 16; off; off >>= 1)
            acc[e] += __shfl_xor_sync(0xffffffffu, acc[e], off);

    if (lane == 0) {
        const int K = *topk_p;
        bool sel[E_EXP];
        int idxs[E_EXP];
#pragma unroll
        for (int e = 0; e < E_EXP; e++) sel[e] = false;
        for (int t = 0; t < K; t++) {
            int best = 0;
            float bv = -3.0e38f;
            for (int e = 0; e < E_EXP; e++)
                if (!sel[e] && acc[e] > bv) { bv = acc[e]; best = e; }
            sel[best] = true;
            idxs[t] = best;
        }
        float mx = acc[idxs[0]];
        for (int t = 1; t < K; t++) mx = fmaxf(mx, acc[idxs[t]]);
        float p[E_EXP], s = 0.f;
        for (int t = 0; t < K; t++) { p[t] = expf(acc[idxs[t]] - mx); s += p[t]; }
        float inv = 1.0f / s;
        for (int e = 0; e < E_EXP; e++) g_wfull[n * E_EXP + e] = 0.f;
        for (int t = 0; t < K; t++) g_wfull[n * E_EXP + idxs[t]] = SCALING_F * p[t] * inv;
    }
}

// ---------------- t = (x @ A^T) * w_full  -> bf16 ----------------------------
__global__ __launch_bounds__(256) void t_kernel(const float* __restrict__ x,
                                                const float* __restrict__ A) {
    __shared__ float xs[2][16][68];
    __shared__ float as[2][16][132];
    const int tx = threadIdx.x & 15, ty = threadIdx.x >> 4;
    const int bm = blockIdx.x * 64;

    const int lrow = threadIdx.x >> 2;
    const int lkv = (threadIdx.x & 3) * 4;
    const float* xg = x + (size_t)(bm + lrow) * D_DIM + lkv;
    const float* ag0 = A + (size_t)lrow * D_DIM + lkv;
    const float* ag1 = A + (size_t)(lrow + 64) * D_DIM + lkv;

    float acc[4][8];
#pragma unroll
    for (int i = 0; i < 4; i++)
#pragma unroll
        for (int j = 0; j < 8; j++) acc[i][j] = 0.f;

    float4 xv, av0, av1;
    xv = *(const float4*)(xg);
    av0 = *(const float4*)(ag0);
    av1 = *(const float4*)(ag1);
    xs[0][lkv + 0][lrow] = xv.x; xs[0][lkv + 1][lrow] = xv.y;
    xs[0][lkv + 2][lrow] = xv.z; xs[0][lkv + 3][lrow] = xv.w;
    as[0][lkv + 0][lrow] = av0.x; as[0][lkv + 1][lrow] = av0.y;
    as[0][lkv + 2][lrow] = av0.z; as[0][lkv + 3][lrow] = av0.w;
    as[0][lkv + 0][lrow + 64] = av1.x; as[0][lkv + 1][lrow + 64] = av1.y;
    as[0][lkv + 2][lrow + 64] = av1.z; as[0][lkv + 3][lrow + 64] = av1.w;
    __syncthreads();

    const int NKT = D_DIM / 16;
    for (int kt = 0; kt < NKT; kt++) {
        int buf = kt & 1;
        if (kt + 1 < NKT) {
            xv = *(const float4*)(xg + (kt + 1) * 16);
            av0 = *(const float4*)(ag0 + (kt + 1) * 16);
            av1 = *(const float4*)(ag1 + (kt + 1) * 16);
        }
#pragma unroll
        for (int kk = 0; kk < 16; kk++) {
            float4 a_ = *(const float4*)&xs[buf][kk][ty * 4];
            float4 b0 = *(const float4*)&as[buf][kk][tx * 8];
            float4 b1 = *(const float4*)&as[buf][kk][tx * 8 + 4];
            float bb[8] = {b0.x, b0.y, b0.z, b0.w, b1.x, b1.y, b1.z, b1.w};
            float aa[4] = {a_.x, a_.y, a_.z, a_.w};
#pragma unroll
            for (int i = 0; i < 4; i++)
#pragma unroll
                for (int j = 0; j < 8; j++) acc[i][j] = fmaf(aa[i], bb[j], acc[i][j]);
        }
        if (kt + 1 < NKT) {
            int nb = buf ^ 1;
            xs[nb][lkv + 0][lrow] = xv.x; xs[nb][lkv + 1][lrow] = xv.y;
            xs[nb][lkv + 2][lrow] = xv.z; xs[nb][lkv + 3][lrow] = xv.w;
            as[nb][lkv + 0][lrow] = av0.x; as[nb][lkv + 1][lrow] = av0.y;
            as[nb][lkv + 2][lrow] = av0.z; as[nb][lkv + 3][lrow] = av0.w;
            as[nb][lkv + 0][lrow + 64] = av1.x; as[nb][lkv + 1][lrow + 64] = av1.y;
            as[nb][lkv + 2][lrow + 64] = av1.z; as[nb][lkv + 3][lrow + 64] = av1.w;
        }
        __syncthreads();
    }

    const int e = tx >> 1;
#pragma unroll
    for (int i = 0; i < 4; i++) {
        int n_ = bm + ty * 4 + i;
        float w = g_wfull[n_ * E_EXP + e];
        uint4 pk;
        pk.x = pack_bf2(acc[i][0] * w, acc[i][1] * w);
        pk.y = pack_bf2(acc[i][2] * w, acc[i][3] * w);
        pk.z = pack_bf2(acc[i][4] * w, acc[i][5] * w);
        pk.w = pack_bf2(acc[i][6] * w, acc[i][7] * w);
        *(uint4*)&g_tbf[(size_t)n_ * EJ + tx * 8] = pk;
    }
}

// ---------------- main mma.sync GEMM -----------------------------------------
// y[bm:+128, bn:+256] = xhi@Whi^T + xhi@Wlo^T + xlo@Whi^T  (K=4096)
//                     + t @ BcatT^T                         (K=128, hi only)
// 512 thr (4x4 warps, 32x64 warp tile), BK=32, 3-stage cp.async pipeline.
// Rows padded to 80B -> ldmatrix conflict-free.
#define ROWB 80
#define AHI_O 0
#define ALO_O 10240
#define BHI_O 20480
#define BLO_O 40960
#define STAGE_B 61440
#define NCH 132        // 128 main + 4 lora chunks
#define DSMEM_TOTAL (3 * STAGE_B)

__device__ __forceinline__ void load_stage(int c, int buf, int bm, int bn, uint32_t sm) {
    const uint32_t sb = sm + buf * STAGE_B;
    const int tid = threadIdx.x;
    if (c < 128) {
        const char* xh = (const char*)g_xhi;
        const char* xl = (const char*)g_xlo;
        const char* wh = (const char*)g_whi;
        const char* wl = (const char*)g_wlo;
        const size_t kofs = (size_t)c * 64;  // bytes into 8192B row
#pragma unroll
        for (int t = 0; t < 6; t++) {
            int idx = tid + t * 512;
            if (idx < 512) {
                int row = idx >> 2, seg = idx & 3;
                cp16(sb + AHI_O + row * ROWB + seg * 16,
                     xh + (size_t)(bm + row) * 8192 + kofs + seg * 16);
            } else if (idx < 1024) {
                int j = idx - 512, row = j >> 2, seg = j & 3;
                cp16(sb + ALO_O + row * ROWB + seg * 16,
                     xl + (size_t)(bm + row) * 8192 + kofs + seg * 16);
            } else if (idx < 2048) {
                int j = idx - 1024, row = j >> 2, seg = j & 3;
                cp16(sb + BHI_O + row * ROWB + seg * 16,
                     wh + (size_t)(bn + row) * 8192 + kofs + seg * 16);
            } else {
                int j = idx - 2048, row = j >> 2, seg = j & 3;
                cp16(sb + BLO_O + row * ROWB + seg * 16,
                     wl + (size_t)(bn + row) * 8192 + kofs + seg * 16);
            }
        }
    } else {
        const char* tp = (const char*)g_tbf;
        const char* bp = (const char*)g_bcatT;
        const size_t kofs = (size_t)(c - 128) * 64;  // bytes into 256B row
#pragma unroll
        for (int t = 0; t < 3; t++) {
            int idx = tid + t * 512;
            if (idx < 512) {
                int row = idx >> 2, seg = idx & 3;
                cp16(sb + AHI_O + row * ROWB + seg * 16,
                     tp + (size_t)(bm + row) * 256 + kofs + seg * 16);
            } else {
                int j = idx - 512, row = j >> 2, seg = j & 3;
                cp16(sb + BHI_O + row * ROWB + seg * 16,
                     bp + (size_t)(bn + row) * 256 + kofs + seg * 16);
            }
        }
    }
    cp_commit();
}

__global__ __launch_bounds__(512, 1) void main_mma_kernel(float* __restrict__ y) {
    extern __shared__ char smem[];
    const uint32_t sm = smem_u32(smem);
    const int tid = threadIdx.x;
    const int wid = tid >> 5, lane = tid & 31;
    const int wm = wid & 3, wn = wid >> 2;          // 4x4 warp grid
    const int bm = blockIdx.y * 128, bn = blockIdx.x * 256;

    // ldmatrix per-lane addressing: group g=lane/8 -> quad; row within tile:
    const int lrow = (lane & 7) + ((lane >> 3) & 1) * 8;  // +8 for odd groups
    const int lkh = (lane >> 4) * 16;                     // +16B for k8..15 quads

    float acc[2][8][4];
#pragma unroll
    for (int mt = 0; mt < 2; mt++)
#pragma unroll
        for (int j = 0; j < 8; j++)
#pragma unroll
            for (int q = 0; q < 4; q++) acc[mt][j][q] = 0.f;

    // prologue: stages for chunks 0,1
    load_stage(0, 0, bm, bn, sm);
    load_stage(1, 1, bm, bn, sm);

    int buf = 0;
    for (int c = 0; c < NCH; c++) {
        cp_wait1();
        __syncthreads();
        // prefetch c+2 into the buffer freed in the previous iteration
        if (c + 2 < NCH) load_stage(c + 2, (c + 2) % 3, bm, bn, sm);
        else cp_commit();  // keep group accounting uniform

        const bool lora = (c >= 128);
        const uint32_t sb = sm + buf * STAGE_B;
        const uint32_t a_base = sb + AHI_O + (wm * 32 + lrow) * ROWB + lkh;
        const uint32_t al_base = sb + ALO_O + (wm * 32 + lrow) * ROWB + lkh;
        const uint32_t b_base = sb + BHI_O + (wn * 64 + lrow) * ROWB + lkh;
        const uint32_t bl_base = sb + BLO_O + (wn * 64 + lrow) * ROWB + lkh;

#pragma unroll
        for (int s = 0; s < 2; s++) {
            const uint32_t so = s * 32;  // k16 step within BK=32 (32B)
            uint32_t ah[2][4], al[2][4], b[4][4];
#pragma unroll
            for (int mt = 0; mt < 2; mt++) ldm4(ah[mt], a_base + mt * 16 * ROWB + so);
            if (!lora)
#pragma unroll
                for (int mt = 0; mt < 2; mt++) ldm4(al[mt], al_base + mt * 16 * ROWB + so);
#pragma unroll
            for (int nt = 0; nt < 4; nt++) ldm4(b[nt], b_base + nt * 16 * ROWB + so);
            // hi*hi (+ lo*hi)
#pragma unroll
            for (int mt = 0; mt < 2; mt++)
#pragma unroll
                for (int nt = 0; nt < 4; nt++) {
                    mma_bf16(acc[mt][nt * 2 + 0], ah[mt], b[nt][0], b[nt][2]);
                    mma_bf16(acc[mt][nt * 2 + 1], ah[mt], b[nt][1], b[nt][3]);
                }
            if (!lora) {
#pragma unroll
                for (int mt = 0; mt < 2; mt++)
#pragma unroll
                    for (int nt = 0; nt < 4; nt++) {
                        mma_bf16(acc[mt][nt * 2 + 0], al[mt], b[nt][0], b[nt][2]);
                        mma_bf16(acc[mt][nt * 2 + 1], al[mt], b[nt][1], b[nt][3]);
                    }
                // hi*lo: reload b from Wlo
#pragma unroll
                for (int nt = 0; nt < 4; nt++) ldm4(b[nt], bl_base + nt * 16 * ROWB + so);
#pragma unroll
                for (int mt = 0; mt < 2; mt++)
#pragma unroll
                    for (int nt = 0; nt < 4; nt++) {
                        mma_bf16(acc[mt][nt * 2 + 0], ah[mt], b[nt][0], b[nt][2]);
                        mma_bf16(acc[mt][nt * 2 + 1], ah[mt], b[nt][1], b[nt][3]);
                    }
            }
        }
        buf = (buf + 1) % 3;
        __syncthreads();
    }

    // ---- epilogue: fragment -> y ----
    const int r0 = bm + wm * 32 + (lane >> 2);
    const int col0 = bn + wn * 64 + (lane & 3) * 2;
#pragma unroll
    for (int mt = 0; mt < 2; mt++)
#pragma unroll
        for (int j = 0; j < 8; j++) {
            int r = r0 + mt * 16;
            int cc = col0 + j * 8;
            *(float2*)&y[(size_t)r * D_DIM + cc] = make_float2(acc[mt][j][0], acc[mt][j][1]);
            *(float2*)&y[(size_t)(r + 8) * D_DIM + cc] = make_float2(acc[mt][j][2], acc[mt][j][3]);
        }
}

// -----------------------------------------------------------------------------
extern "C" void kernel_launch(void* const* d_in, const int* in_sizes, int n_in,
                              void* d_out, int out_size) {
    const float* x = (const float*)d_in[0];
    const float* base_W = (const float*)d_in[1];
    const float* gate_W = (const float*)d_in[2];
    const float* A = (const float*)d_in[3];
    const float* B = (const float*)d_in[4];
    const int* topk = (const int*)d_in[5];
    float* y = (float*)d_out;

    cudaFuncSetAttribute(main_mma_kernel, cudaFuncAttributeMaxDynamicSharedMemorySize,
                         DSMEM_TOTAL);

    split_x_kernel<<<4096, 256>>>(x);
    split_w_kernel<<<4096, 256>>>(base_W);
    bcat_kernel<<<(D_DIM * EJ) / 256, 256>>>(B);
    gate_kernel<<<N_TOK / 4, 128>>>(x, gate_W, topk);
    t_kernel<<<N_TOK / 64, 256>>>(x, A);
    main_mma_kernel<<<dim3(D_DIM / 256, N_TOK / 128), 512, DSMEM_TOTAL>>>(y);
}

// round 9
// speedup vs baseline: 2.2837x; 1.5370x over previous
#include <cuda_runtime.h>
#include <cuda_bf16.h>
#include <cstdint>

#define N_TOK 8192
#define D_DIM 4096
#define E_EXP 8
#define R_RANK 16
#define EJ (E_EXP * R_RANK)   // 128
#define SCALING_F 2.0f

// ---------------- device-global scratch (no allocation allowed) --------------
__device__ float          g_wfull[N_TOK * E_EXP];
__device__ __nv_bfloat16  g_xhi[(size_t)N_TOK * D_DIM];
__device__ __nv_bfloat16  g_xlo[(size_t)N_TOK * D_DIM];
__device__ __nv_bfloat16  g_whi[(size_t)D_DIM * D_DIM];
__device__ __nv_bfloat16  g_wlo[(size_t)D_DIM * D_DIM];
__device__ __nv_bfloat16  g_tbf[(size_t)N_TOK * EJ];     // t in bf16 [8192][128]
__device__ __nv_bfloat16  g_bcatT[(size_t)D_DIM * EJ];   // BcatT[d][j=e*16+r]

// ---------------- helpers ----------------------------------------------------
__device__ __forceinline__ uint32_t smem_u32(const void* p) {
    uint32_t a;
    asm("{ .reg .u64 t; cvta.to.shared.u64 t, %1; cvt.u32.u64 %0, t; }" : "=r"(a) : "l"(p));
    return a;
}
__device__ __forceinline__ void cp16(uint32_t dst, const void* src) {
    asm volatile("cp.async.cg.shared.global [%0], [%1], 16;" :: "r"(dst), "l"(src));
}
__device__ __forceinline__ void cp_commit() {
    asm volatile("cp.async.commit_group;" ::: "memory");
}
__device__ __forceinline__ void cp_wait1() {
    asm volatile("cp.async.wait_group 1;" ::: "memory");
}
__device__ __forceinline__ void ldm4(uint32_t* r, uint32_t addr) {
    asm volatile("ldmatrix.sync.aligned.m8n8.x4.shared.b16 {%0,%1,%2,%3}, [%4];"
                 : "=r"(r[0]), "=r"(r[1]), "=r"(r[2]), "=r"(r[3]) : "r"(addr));
}
__device__ __forceinline__ void mma_bf16(float* c, const uint32_t* a, uint32_t b0,
                                         uint32_t b1) {
    asm volatile(
        "mma.sync.aligned.m16n8k16.row.col.f32.bf16.bf16.f32 "
        "{%0,%1,%2,%3}, {%4,%5,%6,%7}, {%8,%9}, {%0,%1,%2,%3};"
        : "+f"(c[0]), "+f"(c[1]), "+f"(c[2]), "+f"(c[3])
        : "r"(a[0]), "r"(a[1]), "r"(a[2]), "r"(a[3]), "r"(b0), "r"(b1));
}
__device__ __forceinline__ uint32_t pack_bf2(float a, float b) {
    __nv_bfloat162 t = __floats2bfloat162_rn(a, b);
    return *reinterpret_cast<uint32_t*>(&t);
}

// ---------------- conversion kernels -----------------------------------------
__device__ __forceinline__ void split_body(const float* __restrict__ src,
                                           __nv_bfloat16* __restrict__ hi,
                                           __nv_bfloat16* __restrict__ lo, int n4) {
    for (int i = blockIdx.x * blockDim.x + threadIdx.x; i < n4; i += gridDim.x * blockDim.x) {
        float4 v = ((const float4*)src)[i];
        __nv_bfloat16 h0 = __float2bfloat16_rn(v.x), h1 = __float2bfloat16_rn(v.y);
        __nv_bfloat16 h2 = __float2bfloat16_rn(v.z), h3 = __float2bfloat16_rn(v.w);
        float l0 = v.x - __bfloat162float(h0), l1 = v.y - __bfloat162float(h1);
        float l2 = v.z - __bfloat162float(h2), l3 = v.w - __bfloat162float(h3);
        uint2 ph, pl;
        {
            __nv_bfloat162 a = {h0, h1}, b = {h2, h3};
            ph.x = *reinterpret_cast<uint32_t*>(&a);
            ph.y = *reinterpret_cast<uint32_t*>(&b);
        }
        pl.x = pack_bf2(l0, l1);
        pl.y = pack_bf2(l2, l3);
        ((uint2*)hi)[i] = ph;
        ((uint2*)lo)[i] = pl;
    }
}
__global__ __launch_bounds__(256) void split_x_kernel(const float* __restrict__ x) {
    split_body(x, g_xhi, g_xlo, (N_TOK * D_DIM) / 4);
}
__global__ __launch_bounds__(256) void split_w_kernel(const float* __restrict__ w) {
    split_body(w, g_whi, g_wlo, (D_DIM * D_DIM) / 4);
}

__global__ __launch_bounds__(256) void bcat_kernel(const float* __restrict__ B) {
    int i = blockIdx.x * blockDim.x + threadIdx.x;  // 4096*128
    if (i >= D_DIM * EJ) return;
    int d = i >> 7, j = i & 127, e = j >> 4, r = j & 15;
    g_bcatT[(size_t)d * EJ + j] =
        __float2bfloat16_rn(B[(size_t)e * D_DIM * R_RANK + (size_t)d * R_RANK + r]);
}

// ---------------- gate: logits + top-k softmax -> g_wfull --------------------
__global__ __launch_bounds__(128) void gate_kernel(const float* __restrict__ x,
                                                   const float* __restrict__ gw,
                                                   const int* __restrict__ topk_p) {
    __shared__ float sgw[E_EXP][512];
    const int warp = threadIdx.x >> 5, lane = threadIdx.x & 31;
    const int n = blockIdx.x * 4 + warp;

    float acc[E_EXP];
#pragma unroll
    for (int e = 0; e < E_EXP; e++) acc[e] = 0.f;

    for (int kt = 0; kt < D_DIM / 512; kt++) {
        __syncthreads();
        for (int i = threadIdx.x; i < E_EXP * 128; i += blockDim.x) {
            int e = i >> 7, kv = i & 127;
            ((float4*)sgw[e])[kv] = ((const float4*)(gw + e * D_DIM + kt * 512))[kv];
        }
        __syncthreads();
        const float4* xr = (const float4*)(x + (size_t)n * D_DIM + kt * 512);
#pragma unroll 4
        for (int k4 = lane; k4 < 128; k4 += 32) {
            float4 xv = xr[k4];
#pragma unroll
            for (int e = 0; e < E_EXP; e++) {
                float4 wv = ((float4*)sgw[e])[k4];
                acc[e] += xv.x * wv.x + xv.y * wv.y + xv.z * wv.z + xv.w * wv.w;
            }
        }
    }
#pragma unroll
    for (int e = 0; e < E_EXP; e++)
#pragma unroll
        for (int off = 16; off; off >>= 1)
            acc[e] += __shfl_xor_sync(0xffffffffu, acc[e], off);

    if (lane == 0) {
        const int K = *topk_p;
        bool sel[E_EXP];
        int idxs[E_EXP];
#pragma unroll
        for (int e = 0; e < E_EXP; e++) sel[e] = false;
        for (int t = 0; t < K; t++) {
            int best = 0;
            float bv = -3.0e38f;
            for (int e = 0; e < E_EXP; e++)
                if (!sel[e] && acc[e] > bv) { bv = acc[e]; best = e; }
            sel[best] = true;
            idxs[t] = best;
        }
        float mx = acc[idxs[0]];
        for (int t = 1; t < K; t++) mx = fmaxf(mx, acc[idxs[t]]);
        float p[E_EXP], s = 0.f;
        for (int t = 0; t < K; t++) { p[t] = expf(acc[idxs[t]] - mx); s += p[t]; }
        float inv = 1.0f / s;
        for (int e = 0; e < E_EXP; e++) g_wfull[n * E_EXP + e] = 0.f;
        for (int t = 0; t < K; t++) g_wfull[n * E_EXP + idxs[t]] = SCALING_F * p[t] * inv;
    }
}

// ---------------- t = (x @ A^T) * w_full  -> bf16 ----------------------------
__global__ __launch_bounds__(256) void t_kernel(const float* __restrict__ x,
                                                const float* __restrict__ A) {
    __shared__ float xs[2][16][68];
    __shared__ float as[2][16][132];
    const int tx = threadIdx.x & 15, ty = threadIdx.x >> 4;
    const int bm = blockIdx.x * 64;

    const int lrow = threadIdx.x >> 2;
    const int lkv = (threadIdx.x & 3) * 4;
    const float* xg = x + (size_t)(bm + lrow) * D_DIM + lkv;
    const float* ag0 = A + (size_t)lrow * D_DIM + lkv;
    const float* ag1 = A + (size_t)(lrow + 64) * D_DIM + lkv;

    float acc[4][8];
#pragma unroll
    for (int i = 0; i < 4; i++)
#pragma unroll
        for (int j = 0; j < 8; j++) acc[i][j] = 0.f;

    float4 xv, av0, av1;
    xv = *(const float4*)(xg);
    av0 = *(const float4*)(ag0);
    av1 = *(const float4*)(ag1);
    xs[0][lkv + 0][lrow] = xv.x; xs[0][lkv + 1][lrow] = xv.y;
    xs[0][lkv + 2][lrow] = xv.z; xs[0][lkv + 3][lrow] = xv.w;
    as[0][lkv + 0][lrow] = av0.x; as[0][lkv + 1][lrow] = av0.y;
    as[0][lkv + 2][lrow] = av0.z; as[0][lkv + 3][lrow] = av0.w;
    as[0][lkv + 0][lrow + 64] = av1.x; as[0][lkv + 1][lrow + 64] = av1.y;
    as[0][lkv + 2][lrow + 64] = av1.z; as[0][lkv + 3][lrow + 64] = av1.w;
    __syncthreads();

    const int NKT = D_DIM / 16;
    for (int kt = 0; kt < NKT; kt++) {
        int buf = kt & 1;
        if (kt + 1 < NKT) {
            xv = *(const float4*)(xg + (kt + 1) * 16);
            av0 = *(const float4*)(ag0 + (kt + 1) * 16);
            av1 = *(const float4*)(ag1 + (kt + 1) * 16);
        }
#pragma unroll
        for (int kk = 0; kk < 16; kk++) {
            float4 a_ = *(const float4*)&xs[buf][kk][ty * 4];
            float4 b0 = *(const float4*)&as[buf][kk][tx * 8];
            float4 b1 = *(const float4*)&as[buf][kk][tx * 8 + 4];
            float bb[8] = {b0.x, b0.y, b0.z, b0.w, b1.x, b1.y, b1.z, b1.w};
            float aa[4] = {a_.x, a_.y, a_.z, a_.w};
#pragma unroll
            for (int i = 0; i < 4; i++)
#pragma unroll
                for (int j = 0; j < 8; j++) acc[i][j] = fmaf(aa[i], bb[j], acc[i][j]);
        }
        if (kt + 1 < NKT) {
            int nb = buf ^ 1;
            xs[nb][lkv + 0][lrow] = xv.x; xs[nb][lkv + 1][lrow] = xv.y;
            xs[nb][lkv + 2][lrow] = xv.z; xs[nb][lkv + 3][lrow] = xv.w;
            as[nb][lkv + 0][lrow] = av0.x; as[nb][lkv + 1][lrow] = av0.y;
            as[nb][lkv + 2][lrow] = av0.z; as[nb][lkv + 3][lrow] = av0.w;
            as[nb][lkv + 0][lrow + 64] = av1.x; as[nb][lkv + 1][lrow + 64] = av1.y;
            as[nb][lkv + 2][lrow + 64] = av1.z; as[nb][lkv + 3][lrow + 64] = av1.w;
        }
        __syncthreads();
    }

    const int e = tx >> 1;
#pragma unroll
    for (int i = 0; i < 4; i++) {
        int n_ = bm + ty * 4 + i;
        float w = g_wfull[n_ * E_EXP + e];
        uint4 pk;
        pk.x = pack_bf2(acc[i][0] * w, acc[i][1] * w);
        pk.y = pack_bf2(acc[i][2] * w, acc[i][3] * w);
        pk.z = pack_bf2(acc[i][4] * w, acc[i][5] * w);
        pk.w = pack_bf2(acc[i][6] * w, acc[i][7] * w);
        *(uint4*)&g_tbf[(size_t)n_ * EJ + tx * 8] = pk;
    }
}

// ---------------- main mma.sync GEMM -----------------------------------------
// y[bm:+128, bn:+256] = xhi@Whi^T + xhi@Wlo^T + xlo@Whi^T  (K=4096)
//                     + t @ BcatT^T                         (K=128, hi only)
// 512 thr (4x4 warps, 32x64 warp tile), BK=32, 3-stage cp.async pipeline.
// Rows padded to 80B -> ldmatrix conflict-free.
#define ROWB 80
#define AHI_O 0
#define ALO_O 10240
#define BHI_O 20480
#define BLO_O 40960
#define STAGE_B 61440
#define NCH 132        // 128 main + 4 lora chunks
#define DSMEM_TOTAL (3 * STAGE_B)

__device__ __forceinline__ void load_stage(int c, int buf, int bm, int bn, uint32_t sm) {
    const uint32_t sb = sm + buf * STAGE_B;
    const int tid = threadIdx.x;
    if (c < 128) {
        const char* xh = (const char*)g_xhi;
        const char* xl = (const char*)g_xlo;
        const char* wh = (const char*)g_whi;
        const char* wl = (const char*)g_wlo;
        const size_t kofs = (size_t)c * 64;  // bytes into 8192B row
#pragma unroll
        for (int t = 0; t < 6; t++) {
            int idx = tid + t * 512;
            if (idx < 512) {
                int row = idx >> 2, seg = idx & 3;
                cp16(sb + AHI_O + row * ROWB + seg * 16,
                     xh + (size_t)(bm + row) * 8192 + kofs + seg * 16);
            } else if (idx < 1024) {
                int j = idx - 512, row = j >> 2, seg = j & 3;
                cp16(sb + ALO_O + row * ROWB + seg * 16,
                     xl + (size_t)(bm + row) * 8192 + kofs + seg * 16);
            } else if (idx < 2048) {
                int j = idx - 1024, row = j >> 2, seg = j & 3;
                cp16(sb + BHI_O + row * ROWB + seg * 16,
                     wh + (size_t)(bn + row) * 8192 + kofs + seg * 16);
            } else {
                int j = idx - 2048, row = j >> 2, seg = j & 3;
                cp16(sb + BLO_O + row * ROWB + seg * 16,
                     wl + (size_t)(bn + row) * 8192 + kofs + seg * 16);
            }
        }
    } else {
        const char* tp = (const char*)g_tbf;
        const char* bp = (const char*)g_bcatT;
        const size_t kofs = (size_t)(c - 128) * 64;  // bytes into 256B row
#pragma unroll
        for (int t = 0; t < 3; t++) {
            int idx = tid + t * 512;
            if (idx < 512) {
                int row = idx >> 2, seg = idx & 3;
                cp16(sb + AHI_O + row * ROWB + seg * 16,
                     tp + (size_t)(bm + row) * 256 + kofs + seg * 16);
            } else {
                int j = idx - 512, row = j >> 2, seg = j & 3;
                cp16(sb + BHI_O + row * ROWB + seg * 16,
                     bp + (size_t)(bn + row) * 256 + kofs + seg * 16);
            }
        }
    }
    cp_commit();
}

__global__ __launch_bounds__(512, 1) void main_mma_kernel(float* __restrict__ y) {
    extern __shared__ char smem[];
    const uint32_t sm = smem_u32(smem);
    const int tid = threadIdx.x;
    const int wid = tid >> 5, lane = tid & 31;
    const int wm = wid & 3, wn = wid >> 2;          // 4x4 warp grid
    const int bm = blockIdx.y * 128, bn = blockIdx.x * 256;

    const int lrow = (lane & 7) + ((lane >> 3) & 1) * 8;
    const int lkh = (lane >> 4) * 16;

    float acc[2][8][4];
#pragma unroll
    for (int mt = 0; mt < 2; mt++)
#pragma unroll
        for (int j = 0; j < 8; j++)
#pragma unroll
            for (int q = 0; q < 4; q++) acc[mt][j][q] = 0.f;

    load_stage(0, 0, bm, bn, sm);
    load_stage(1, 1, bm, bn, sm);

    int buf = 0;
    for (int c = 0; c < NCH; c++) {
        cp_wait1();
        __syncthreads();
        // prefetch c+2 into the buffer freed in the previous iteration
        if (c + 2 < NCH) load_stage(c + 2, (c + 2) % 3, bm, bn, sm);
        else cp_commit();  // keep group accounting uniform

        const bool lora = (c >= 128);
        const uint32_t sb = sm + buf * STAGE_B;
        const uint32_t a_base = sb + AHI_O + (wm * 32 + lrow) * ROWB + lkh;
        const uint32_t al_base = sb + ALO_O + (wm * 32 + lrow) * ROWB + lkh;
        const uint32_t b_base = sb + BHI_O + (wn * 64 + lrow) * ROWB + lkh;
        const uint32_t bl_base = sb + BLO_O + (wn * 64 + lrow) * ROWB + lkh;

#pragma unroll
        for (int s = 0; s < 2; s++) {
            const uint32_t so = s * 32;  // k16 step within BK=32 (32B)
            uint32_t ah[2][4], al[2][4], b[4][4];
#pragma unroll
            for (int mt = 0; mt < 2; mt++) ldm4(ah[mt], a_base + mt * 16 * ROWB + so);
            if (!lora)
#pragma unroll
                for (int mt = 0; mt < 2; mt++) ldm4(al[mt], al_base + mt * 16 * ROWB + so);
#pragma unroll
            for (int nt = 0; nt < 4; nt++) ldm4(b[nt], b_base + nt * 16 * ROWB + so);
            // hi*hi (+ lo*hi)
#pragma unroll
            for (int mt = 0; mt < 2; mt++)
#pragma unroll
                for (int nt = 0; nt < 4; nt++) {
                    mma_bf16(acc[mt][nt * 2 + 0], ah[mt], b[nt][0], b[nt][2]);
                    mma_bf16(acc[mt][nt * 2 + 1], ah[mt], b[nt][1], b[nt][3]);
                }
            if (!lora) {
#pragma unroll
                for (int mt = 0; mt < 2; mt++)
#pragma unroll
                    for (int nt = 0; nt < 4; nt++) {
                        mma_bf16(acc[mt][nt * 2 + 0], al[mt], b[nt][0], b[nt][2]);
                        mma_bf16(acc[mt][nt * 2 + 1], al[mt], b[nt][1], b[nt][3]);
                    }
                // hi*lo: reload b from Wlo
#pragma unroll
                for (int nt = 0; nt < 4; nt++) ldm4(b[nt], bl_base + nt * 16 * ROWB + so);
#pragma unroll
                for (int mt = 0; mt < 2; mt++)
#pragma unroll
                    for (int nt = 0; nt < 4; nt++) {
                        mma_bf16(acc[mt][nt * 2 + 0], ah[mt], b[nt][0], b[nt][2]);
                        mma_bf16(acc[mt][nt * 2 + 1], ah[mt], b[nt][1], b[nt][3]);
                    }
            }
        }
        buf = (buf + 1) % 3;
        __syncthreads();
    }

    // ---- epilogue: fragment -> y ----
    const int r0 = bm + wm * 32 + (lane >> 2);
    const int col0 = bn + wn * 64 + (lane & 3) * 2;
#pragma unroll
    for (int mt = 0; mt < 2; mt++)
#pragma unroll
        for (int j = 0; j < 8; j++) {
            int r = r0 + mt * 16;
            int cc = col0 + j * 8;
            *(float2*)&y[(size_t)r * D_DIM + cc] = make_float2(acc[mt][j][0], acc[mt][j][1]);
            *(float2*)&y[(size_t)(r + 8) * D_DIM + cc] = make_float2(acc[mt][j][2], acc[mt][j][3]);
        }
}

// -----------------------------------------------------------------------------
extern "C" void kernel_launch(void* const* d_in, const int* in_sizes, int n_in,
                              void* d_out, int out_size) {
    const float* x = (const float*)d_in[0];
    const float* base_W = (const float*)d_in[1];
    const float* gate_W = (const float*)d_in[2];
    const float* A = (const float*)d_in[3];
    const float* B = (const float*)d_in[4];
    const int* topk = (const int*)d_in[5];
    float* y = (float*)d_out;

    cudaFuncSetAttribute(main_mma_kernel, cudaFuncAttributeMaxDynamicSharedMemorySize,
                         DSMEM_TOTAL);

    split_x_kernel<<<4096, 256>>>(x);
    split_w_kernel<<<4096, 256>>>(base_W);
    bcat_kernel<<<(D_DIM * EJ) / 256, 256>>>(B);
    gate_kernel<<<N_TOK / 4, 128>>>(x, gate_W, topk);
    t_kernel<<<N_TOK / 64, 256>>>(x, A);
    main_mma_kernel<<<dim3(D_DIM / 256, N_TOK / 128), 512, DSMEM_TOTAL>>>(y);
}

// round 11
// speedup vs baseline: 2.2866x; 1.0013x over previous
#include <cuda_runtime.h>
#include <cuda_bf16.h>
#include <cstdint>

#define N_TOK 8192
#define D_DIM 4096
#define E_EXP 8
#define R_RANK 16
#define EJ (E_EXP * R_RANK)   // 128
#define SCALING_F 2.0f

// ---------------- device-global scratch (no allocation allowed) --------------
__device__ float          g_wfull[N_TOK * E_EXP];
__device__ __nv_bfloat16  g_xhi[(size_t)N_TOK * D_DIM];
__device__ __nv_bfloat16  g_xlo[(size_t)N_TOK * D_DIM];
__device__ __nv_bfloat16  g_whi[(size_t)D_DIM * D_DIM];
__device__ __nv_bfloat16  g_wlo[(size_t)D_DIM * D_DIM];
__device__ __nv_bfloat16  g_tbf[(size_t)N_TOK * EJ];     // t in bf16 [8192][128]
__device__ __nv_bfloat16  g_bcatT[(size_t)D_DIM * EJ];   // BcatT[d][j=e*16+r]

// ---------------- helpers ----------------------------------------------------
__device__ __forceinline__ uint32_t smem_u32(const void* p) {
    uint32_t a;
    asm("{ .reg .u64 t; cvta.to.shared.u64 t, %1; cvt.u32.u64 %0, t; }" : "=r"(a) : "l"(p));
    return a;
}
__device__ __forceinline__ void cp16(uint32_t dst, const void* src) {
    asm volatile("cp.async.cg.shared.global [%0], [%1], 16;" :: "r"(dst), "l"(src));
}
__device__ __forceinline__ void cp_commit() {
    asm volatile("cp.async.commit_group;" ::: "memory");
}
__device__ __forceinline__ void cp_wait1() {
    asm volatile("cp.async.wait_group 1;" ::: "memory");
}
__device__ __forceinline__ void ldm4(uint32_t* r, uint32_t addr) {
    asm volatile("ldmatrix.sync.aligned.m8n8.x4.shared.b16 {%0,%1,%2,%3}, [%4];"
                 : "=r"(r[0]), "=r"(r[1]), "=r"(r[2]), "=r"(r[3]) : "r"(addr));
}
__device__ __forceinline__ void mma_bf16(float* c, const uint32_t* a, uint32_t b0,
                                         uint32_t b1) {
    asm volatile(
        "mma.sync.aligned.m16n8k16.row.col.f32.bf16.bf16.f32 "
        "{%0,%1,%2,%3}, {%4,%5,%6,%7}, {%8,%9}, {%0,%1,%2,%3};"
        : "+f"(c[0]), "+f"(c[1]), "+f"(c[2]), "+f"(c[3])
        : "r"(a[0]), "r"(a[1]), "r"(a[2]), "r"(a[3]), "r"(b0), "r"(b1));
}
__device__ __forceinline__ uint32_t pack_bf2(float a, float b) {
    __nv_bfloat162 t = __floats2bfloat162_rn(a, b);
    return *reinterpret_cast<uint32_t*>(&t);
}

// ---------------- prep: split x, split W, build BcatT (ONE kernel) -----------
#define NX4 ((N_TOK * D_DIM) / 4)            // 8388608 float4 units
#define NW4 ((D_DIM * D_DIM) / 4)            // 4194304
#define NBC (D_DIM * EJ)                     // 524288
#define NPREP (NX4 + NW4 + NBC)

__device__ __forceinline__ void split4(const float* __restrict__ src,
                                       __nv_bfloat16* __restrict__ hi,
                                       __nv_bfloat16* __restrict__ lo, int i) {
    float4 v = ((const float4*)src)[i];
    __nv_bfloat16 h0 = __float2bfloat16_rn(v.x), h1 = __float2bfloat16_rn(v.y);
    __nv_bfloat16 h2 = __float2bfloat16_rn(v.z), h3 = __float2bfloat16_rn(v.w);
    uint2 ph, pl;
    {
        __nv_bfloat162 a = {h0, h1}, b = {h2, h3};
        ph.x = *reinterpret_cast<uint32_t*>(&a);
        ph.y = *reinterpret_cast<uint32_t*>(&b);
    }
    pl.x = pack_bf2(v.x - __bfloat162float(h0), v.y - __bfloat162float(h1));
    pl.y = pack_bf2(v.z - __bfloat162float(h2), v.w - __bfloat162float(h3));
    ((uint2*)hi)[i] = ph;
    ((uint2*)lo)[i] = pl;
}

__global__ __launch_bounds__(256) void prep_kernel(const float* __restrict__ x,
                                                   const float* __restrict__ W,
                                                   const float* __restrict__ B) {
    for (int i = blockIdx.x * blockDim.x + threadIdx.x; i < NPREP;
         i += gridDim.x * blockDim.x) {
        if (i < NX4) {
            split4(x, g_xhi, g_xlo, i);
        } else if (i < NX4 + NW4) {
            split4(W, g_whi, g_wlo, i - NX4);
        } else {
            int j2 = i - NX4 - NW4;               // [0, 4096*128)
            int d = j2 >> 7, j = j2 & 127, e = j >> 4, r = j & 15;
            g_bcatT[(size_t)d * EJ + j] = __float2bfloat16_rn(
                B[(size_t)e * D_DIM * R_RANK + (size_t)d * R_RANK + r]);
        }
    }
}

// ---------------- gate: logits + top-k softmax -> g_wfull (R9-identical) -----
__global__ __launch_bounds__(128) void gate_kernel(const float* __restrict__ x,
                                                   const float* __restrict__ gw,
                                                   const int* __restrict__ topk_p) {
    __shared__ float sgw[E_EXP][512];
    const int warp = threadIdx.x >> 5, lane = threadIdx.x & 31;
    const int n = blockIdx.x * 4 + warp;

    float acc[E_EXP];
#pragma unroll
    for (int e = 0; e < E_EXP; e++) acc[e] = 0.f;

    for (int kt = 0; kt < D_DIM / 512; kt++) {
        __syncthreads();
        for (int i = threadIdx.x; i < E_EXP * 128; i += blockDim.x) {
            int e = i >> 7, kv = i & 127;
            ((float4*)sgw[e])[kv] = ((const float4*)(gw + e * D_DIM + kt * 512))[kv];
        }
        __syncthreads();
        const float4* xr = (const float4*)(x + (size_t)n * D_DIM + kt * 512);
#pragma unroll 4
        for (int k4 = lane; k4 < 128; k4 += 32) {
            float4 xv = xr[k4];
#pragma unroll
            for (int e = 0; e < E_EXP; e++) {
                float4 wv = ((float4*)sgw[e])[k4];
                acc[e] += xv.x * wv.x + xv.y * wv.y + xv.z * wv.z + xv.w * wv.w;
            }
        }
    }
#pragma unroll
    for (int e = 0; e < E_EXP; e++)
#pragma unroll
        for (int off = 16; off; off >>= 1)
            acc[e] += __shfl_xor_sync(0xffffffffu, acc[e], off);

    if (lane == 0) {
        const int K = *topk_p;
        bool sel[E_EXP];
        int idxs[E_EXP];
#pragma unroll
        for (int e = 0; e < E_EXP; e++) sel[e] = false;
        for (int t = 0; t < K; t++) {
            int best = 0;
            float bv = -3.0e38f;
            for (int e = 0; e < E_EXP; e++)
                if (!sel[e] && acc[e] > bv) { bv = acc[e]; best = e; }
            sel[best] = true;
            idxs[t] = best;
        }
        float mx = acc[idxs[0]];
        for (int t = 1; t < K; t++) mx = fmaxf(mx, acc[idxs[t]]);
        float p[E_EXP], s = 0.f;
        for (int t = 0; t < K; t++) { p[t] = expf(acc[idxs[t]] - mx); s += p[t]; }
        float inv = 1.0f / s;
        for (int e = 0; e < E_EXP; e++) g_wfull[n * E_EXP + e] = 0.f;
        for (int t = 0; t < K; t++) g_wfull[n * E_EXP + idxs[t]] = SCALING_F * p[t] * inv;
    }
}

// ---------------- t = (x @ A^T) * w_full  -> bf16 (R9-identical) -------------
__global__ __launch_bounds__(256) void t_kernel(const float* __restrict__ x,
                                                const float* __restrict__ A) {
    __shared__ float xs[2][16][68];
    __shared__ float as[2][16][132];
    const int tx = threadIdx.x & 15, ty = threadIdx.x >> 4;
    const int bm = blockIdx.x * 64;

    const int lrow = threadIdx.x >> 2;
    const int lkv = (threadIdx.x & 3) * 4;
    const float* xg = x + (size_t)(bm + lrow) * D_DIM + lkv;
    const float* ag0 = A + (size_t)lrow * D_DIM + lkv;
    const float* ag1 = A + (size_t)(lrow + 64) * D_DIM + lkv;

    float acc[4][8];
#pragma unroll
    for (int i = 0; i < 4; i++)
#pragma unroll
        for (int j = 0; j < 8; j++) acc[i][j] = 0.f;

    float4 xv, av0, av1;
    xv = *(const float4*)(xg);
    av0 = *(const float4*)(ag0);
    av1 = *(const float4*)(ag1);
    xs[0][lkv + 0][lrow] = xv.x; xs[0][lkv + 1][lrow] = xv.y;
    xs[0][lkv + 2][lrow] = xv.z; xs[0][lkv + 3][lrow] = xv.w;
    as[0][lkv + 0][lrow] = av0.x; as[0][lkv + 1][lrow] = av0.y;
    as[0][lkv + 2][lrow] = av0.z; as[0][lkv + 3][lrow] = av0.w;
    as[0][lkv + 0][lrow + 64] = av1.x; as[0][lkv + 1][lrow + 64] = av1.y;
    as[0][lkv + 2][lrow + 64] = av1.z; as[0][lkv + 3][lrow + 64] = av1.w;
    __syncthreads();

    const int NKT = D_DIM / 16;
    for (int kt = 0; kt < NKT; kt++) {
        int buf = kt & 1;
        if (kt + 1 < NKT) {
            xv = *(const float4*)(xg + (kt + 1) * 16);
            av0 = *(const float4*)(ag0 + (kt + 1) * 16);
            av1 = *(const float4*)(ag1 + (kt + 1) * 16);
        }
#pragma unroll
        for (int kk = 0; kk < 16; kk++) {
            float4 a_ = *(const float4*)&xs[buf][kk][ty * 4];
            float4 b0 = *(const float4*)&as[buf][kk][tx * 8];
            float4 b1 = *(const float4*)&as[buf][kk][tx * 8 + 4];
            float bb[8] = {b0.x, b0.y, b0.z, b0.w, b1.x, b1.y, b1.z, b1.w};
            float aa[4] = {a_.x, a_.y, a_.z, a_.w};
#pragma unroll
            for (int i = 0; i < 4; i++)
#pragma unroll
                for (int j = 0; j < 8; j++) acc[i][j] = fmaf(aa[i], bb[j], acc[i][j]);
        }
        if (kt + 1 < NKT) {
            int nb = buf ^ 1;
            xs[nb][lkv + 0][lrow] = xv.x; xs[nb][lkv + 1][lrow] = xv.y;
            xs[nb][lkv + 2][lrow] = xv.z; xs[nb][lkv + 3][lrow] = xv.w;
            as[nb][lkv + 0][lrow] = av0.x; as[nb][lkv + 1][lrow] = av0.y;
            as[nb][lkv + 2][lrow] = av0.z; as[nb][lkv + 3][lrow] = av0.w;
            as[nb][lkv + 0][lrow + 64] = av1.x; as[nb][lkv + 1][lrow + 64] = av1.y;
            as[nb][lkv + 2][lrow + 64] = av1.z; as[nb][lkv + 3][lrow + 64] = av1.w;
        }
        __syncthreads();
    }

    const int e = tx >> 1;
#pragma unroll
    for (int i = 0; i < 4; i++) {
        int n_ = bm + ty * 4 + i;
        float w = g_wfull[n_ * E_EXP + e];
        uint4 pk;
        pk.x = pack_bf2(acc[i][0] * w, acc[i][1] * w);
        pk.y = pack_bf2(acc[i][2] * w, acc[i][3] * w);
        pk.z = pack_bf2(acc[i][4] * w, acc[i][5] * w);
        pk.w = pack_bf2(acc[i][6] * w, acc[i][7] * w);
        *(uint4*)&g_tbf[(size_t)n_ * EJ + tx * 8] = pk;
    }
}

// ---------------- main mma.sync GEMM (R9-identical) --------------------------
// y[bm:+128, bn:+256] = xhi@Whi^T + xhi@Wlo^T + xlo@Whi^T  (K=4096)
//                     + t @ BcatT^T                         (K=128, hi only)
// 512 thr (4x4 warps, 32x64 warp tile), BK=32, 3-stage cp.async pipeline.
// Rows padded to 80B -> ldmatrix conflict-free.
#define ROWB 80
#define AHI_O 0
#define ALO_O 10240
#define BHI_O 20480
#define BLO_O 40960
#define STAGE_B 61440
#define NCH 132        // 128 main + 4 lora chunks
#define DSMEM_TOTAL (3 * STAGE_B)

__device__ __forceinline__ void load_stage(int c, int buf, int bm, int bn, uint32_t sm) {
    const uint32_t sb = sm + buf * STAGE_B;
    const int tid = threadIdx.x;
    if (c < 128) {
        const char* xh = (const char*)g_xhi;
        const char* xl = (const char*)g_xlo;
        const char* wh = (const char*)g_whi;
        const char* wl = (const char*)g_wlo;
        const size_t kofs = (size_t)c * 64;  // bytes into 8192B row
#pragma unroll
        for (int t = 0; t < 6; t++) {
            int idx = tid + t * 512;
            if (idx < 512) {
                int row = idx >> 2, seg = idx & 3;
                cp16(sb + AHI_O + row * ROWB + seg * 16,
                     xh + (size_t)(bm + row) * 8192 + kofs + seg * 16);
            } else if (idx < 1024) {
                int j = idx - 512, row = j >> 2, seg = j & 3;
                cp16(sb + ALO_O + row * ROWB + seg * 16,
                     xl + (size_t)(bm + row) * 8192 + kofs + seg * 16);
            } else if (idx < 2048) {
                int j = idx - 1024, row = j >> 2, seg = j & 3;
                cp16(sb + BHI_O + row * ROWB + seg * 16,
                     wh + (size_t)(bn + row) * 8192 + kofs + seg * 16);
            } else {
                int j = idx - 2048, row = j >> 2, seg = j & 3;
                cp16(sb + BLO_O + row * ROWB + seg * 16,
                     wl + (size_t)(bn + row) * 8192 + kofs + seg * 16);
            }
        }
    } else {
        const char* tp = (const char*)g_tbf;
        const char* bp = (const char*)g_bcatT;
        const size_t kofs = (size_t)(c - 128) * 64;  // bytes into 256B row
#pragma unroll
        for (int t = 0; t < 3; t++) {
            int idx = tid + t * 512;
            if (idx < 512) {
                int row = idx >> 2, seg = idx & 3;
                cp16(sb + AHI_O + row * ROWB + seg * 16,
                     tp + (size_t)(bm + row) * 256 + kofs + seg * 16);
            } else {
                int j = idx - 512, row = j >> 2, seg = j & 3;
                cp16(sb + BHI_O + row * ROWB + seg * 16,
                     bp + (size_t)(bn + row) * 256 + kofs + seg * 16);
            }
        }
    }
    cp_commit();
}

__global__ __launch_bounds__(512, 1) void main_mma_kernel(float* __restrict__ y) {
    extern __shared__ char smem[];
    const uint32_t sm = smem_u32(smem);
    const int tid = threadIdx.x;
    const int wid = tid >> 5, lane = tid & 31;
    const int wm = wid & 3, wn = wid >> 2;          // 4x4 warp grid
    const int bm = blockIdx.y * 128, bn = blockIdx.x * 256;

    const int lrow = (lane & 7) + ((lane >> 3) & 1) * 8;
    const int lkh = (lane >> 4) * 16;

    float acc[2][8][4];
#pragma unroll
    for (int mt = 0; mt < 2; mt++)
#pragma unroll
        for (int j = 0; j < 8; j++)
#pragma unroll
            for (int q = 0; q < 4; q++) acc[mt][j][q] = 0.f;

    load_stage(0, 0, bm, bn, sm);
    load_stage(1, 1, bm, bn, sm);

    int buf = 0;
    for (int c = 0; c < NCH; c++) {
        cp_wait1();
        __syncthreads();
        // prefetch c+2 into the buffer freed in the previous iteration
        if (c + 2 < NCH) load_stage(c + 2, (c + 2) % 3, bm, bn, sm);
        else cp_commit();  // keep group accounting uniform

        const bool lora = (c >= 128);
        const uint32_t sb = sm + buf * STAGE_B;
        const uint32_t a_base = sb + AHI_O + (wm * 32 + lrow) * ROWB + lkh;
        const uint32_t al_base = sb + ALO_O + (wm * 32 + lrow) * ROWB + lkh;
        const uint32_t b_base = sb + BHI_O + (wn * 64 + lrow) * ROWB + lkh;
        const uint32_t bl_base = sb + BLO_O + (wn * 64 + lrow) * ROWB + lkh;

#pragma unroll
        for (int s = 0; s < 2; s++) {
            const uint32_t so = s * 32;  // k16 step within BK=32 (32B)
            uint32_t ah[2][4], al[2][4], b[4][4];
#pragma unroll
            for (int mt = 0; mt < 2; mt++) ldm4(ah[mt], a_base + mt * 16 * ROWB + so);
            if (!lora)
#pragma unroll
                for (int mt = 0; mt < 2; mt++) ldm4(al[mt], al_base + mt * 16 * ROWB + so);
#pragma unroll
            for (int nt = 0; nt < 4; nt++) ldm4(b[nt], b_base + nt * 16 * ROWB + so);
            // hi*hi (+ lo*hi)
#pragma unroll
            for (int mt = 0; mt < 2; mt++)
#pragma unroll
                for (int nt = 0; nt < 4; nt++) {
                    mma_bf16(acc[mt][nt * 2 + 0], ah[mt], b[nt][0], b[nt][2]);
                    mma_bf16(acc[mt][nt * 2 + 1], ah[mt], b[nt][1], b[nt][3]);
                }
            if (!lora) {
#pragma unroll
                for (int mt = 0; mt < 2; mt++)
#pragma unroll
                    for (int nt = 0; nt < 4; nt++) {
                        mma_bf16(acc[mt][nt * 2 + 0], al[mt], b[nt][0], b[nt][2]);
                        mma_bf16(acc[mt][nt * 2 + 1], al[mt], b[nt][1], b[nt][3]);
                    }
                // hi*lo: reload b from Wlo
#pragma unroll
                for (int nt = 0; nt < 4; nt++) ldm4(b[nt], bl_base + nt * 16 * ROWB + so);
#pragma unroll
                for (int mt = 0; mt < 2; mt++)
#pragma unroll
                    for (int nt = 0; nt < 4; nt++) {
                        mma_bf16(acc[mt][nt * 2 + 0], ah[mt], b[nt][0], b[nt][2]);
                        mma_bf16(acc[mt][nt * 2 + 1], ah[mt], b[nt][1], b[nt][3]);
                    }
            }
        }
        buf = (buf + 1) % 3;
        __syncthreads();
    }

    // ---- epilogue: fragment -> y ----
    const int r0 = bm + wm * 32 + (lane >> 2);
    const int col0 = bn + wn * 64 + (lane & 3) * 2;
#pragma unroll
    for (int mt = 0; mt < 2; mt++)
#pragma unroll
        for (int j = 0; j < 8; j++) {
            int r = r0 + mt * 16;
            int cc = col0 + j * 8;
            *(float2*)&y[(size_t)r * D_DIM + cc] = make_float2(acc[mt][j][0], acc[mt][j][1]);
            *(float2*)&y[(size_t)(r + 8) * D_DIM + cc] = make_float2(acc[mt][j][2], acc[mt][j][3]);
        }
}

// -----------------------------------------------------------------------------
extern "C" void kernel_launch(void* const* d_in, const int* in_sizes, int n_in,
                              void* d_out, int out_size) {
    const float* x = (const float*)d_in[0];
    const float* base_W = (const float*)d_in[1];
    const float* gate_W = (const float*)d_in[2];
    const float* A = (const float*)d_in[3];
    const float* B = (const float*)d_in[4];
    const int* topk = (const int*)d_in[5];
    float* y = (float*)d_out;

    cudaFuncSetAttribute(main_mma_kernel, cudaFuncAttributeMaxDynamicSharedMemorySize,
                         DSMEM_TOTAL);

    // 4 launches: with the harness's 2 internal launches, main_mma_kernel lands
    // on global launch index 5 -> ncu (-s 5 -c 1) finally profiles MAIN.
    prep_kernel<<<2048, 256>>>(x, base_W, B);
    gate_kernel<<<N_TOK / 4, 128>>>(x, gate_W, topk);
    t_kernel<<<N_TOK / 64, 256>>>(x, A);
    main_mma_kernel<<<dim3(D_DIM / 256, N_TOK / 128), 512, DSMEM_TOTAL>>>(y);
}

// round 12
// speedup vs baseline: 2.4442x; 1.0689x over previous
#include <cuda_runtime.h>
#include <cuda_bf16.h>
#include <cstdint>

#define N_TOK 8192
#define D_DIM 4096
#define E_EXP 8
#define R_RANK 16
#define EJ (E_EXP * R_RANK)   // 128
#define SCALING_F 2.0f

// ---------------- device-global scratch (no allocation allowed) --------------
__device__ float          g_wfull[N_TOK * E_EXP];
__device__ __nv_bfloat16  g_xhi[(size_t)N_TOK * D_DIM];
__device__ __nv_bfloat16  g_xlo[(size_t)N_TOK * D_DIM];
__device__ __nv_bfloat16  g_whi[(size_t)D_DIM * D_DIM];
__device__ __nv_bfloat16  g_wlo[(size_t)D_DIM * D_DIM];
__device__ __nv_bfloat16  g_tbf[(size_t)N_TOK * EJ];     // t in bf16 [8192][128]
__device__ __nv_bfloat16  g_bcatT[(size_t)D_DIM * EJ];   // BcatT[d][j=e*16+r]

// ---------------- helpers ----------------------------------------------------
__device__ __forceinline__ uint32_t smem_u32(const void* p) {
    uint32_t a;
    asm("{ .reg .u64 t; cvta.to.shared.u64 t, %1; cvt.u32.u64 %0, t; }" : "=r"(a) : "l"(p));
    return a;
}
__device__ __forceinline__ void cp16(uint32_t dst, const void* src) {
    asm volatile("cp.async.cg.shared.global [%0], [%1], 16;" :: "r"(dst), "l"(src));
}
__device__ __forceinline__ void cp_commit() {
    asm volatile("cp.async.commit_group;" ::: "memory");
}
__device__ __forceinline__ void cp_wait1() {
    asm volatile("cp.async.wait_group 1;" ::: "memory");
}
__device__ __forceinline__ void ldm4(uint32_t* r, uint32_t addr) {
    asm volatile("ldmatrix.sync.aligned.m8n8.x4.shared.b16 {%0,%1,%2,%3}, [%4];"
                 : "=r"(r[0]), "=r"(r[1]), "=r"(r[2]), "=r"(r[3]) : "r"(addr));
}
__device__ __forceinline__ void mma_bf16(float* c, const uint32_t* a, uint32_t b0,
                                         uint32_t b1) {
    asm volatile(
        "mma.sync.aligned.m16n8k16.row.col.f32.bf16.bf16.f32 "
        "{%0,%1,%2,%3}, {%4,%5,%6,%7}, {%8,%9}, {%0,%1,%2,%3};"
        : "+f"(c[0]), "+f"(c[1]), "+f"(c[2]), "+f"(c[3])
        : "r"(a[0]), "r"(a[1]), "r"(a[2]), "r"(a[3]), "r"(b0), "r"(b1));
}
__device__ __forceinline__ uint32_t pack_bf2(float a, float b) {
    __nv_bfloat162 t = __floats2bfloat162_rn(a, b);
    return *reinterpret_cast<uint32_t*>(&t);
}

// ---------------- prep: split x, split W, build BcatT (ONE kernel) -----------
#define NX4 ((N_TOK * D_DIM) / 4)            // 8388608 float4 units
#define NW4 ((D_DIM * D_DIM) / 4)            // 4194304
#define NBC (D_DIM * EJ)                     // 524288
#define NPREP (NX4 + NW4 + NBC)

__device__ __forceinline__ void split4(const float* __restrict__ src,
                                       __nv_bfloat16* __restrict__ hi,
                                       __nv_bfloat16* __restrict__ lo, int i) {
    float4 v = ((const float4*)src)[i];
    __nv_bfloat16 h0 = __float2bfloat16_rn(v.x), h1 = __float2bfloat16_rn(v.y);
    __nv_bfloat16 h2 = __float2bfloat16_rn(v.z), h3 = __float2bfloat16_rn(v.w);
    uint2 ph, pl;
    {
        __nv_bfloat162 a = {h0, h1}, b = {h2, h3};
        ph.x = *reinterpret_cast<uint32_t*>(&a);
        ph.y = *reinterpret_cast<uint32_t*>(&b);
    }
    pl.x = pack_bf2(v.x - __bfloat162float(h0), v.y - __bfloat162float(h1));
    pl.y = pack_bf2(v.z - __bfloat162float(h2), v.w - __bfloat162float(h3));
    ((uint2*)hi)[i] = ph;
    ((uint2*)lo)[i] = pl;
}

__global__ __launch_bounds__(256) void prep_kernel(const float* __restrict__ x,
                                                   const float* __restrict__ W,
                                                   const float* __restrict__ B) {
    for (int i = blockIdx.x * blockDim.x + threadIdx.x; i < NPREP;
         i += gridDim.x * blockDim.x) {
        if (i < NX4) {
            split4(x, g_xhi, g_xlo, i);
        } else if (i < NX4 + NW4) {
            split4(W, g_whi, g_wlo, i - NX4);
        } else {
            int j2 = i - NX4 - NW4;               // [0, 4096*128)
            int d = j2 >> 7, j = j2 & 127, e = j >> 4, r = j & 15;
            g_bcatT[(size_t)d * EJ + j] = __float2bfloat16_rn(
                B[(size_t)e * D_DIM * R_RANK + (size_t)d * R_RANK + r]);
        }
    }
}

// ---------------- gate: logits + top-k softmax -> g_wfull --------------------
__global__ __launch_bounds__(128) void gate_kernel(const float* __restrict__ x,
                                                   const float* __restrict__ gw,
                                                   const int* __restrict__ topk_p) {
    __shared__ float sgw[E_EXP][512];
    const int warp = threadIdx.x >> 5, lane = threadIdx.x & 31;
    const int n = blockIdx.x * 4 + warp;

    float acc[E_EXP];
#pragma unroll
    for (int e = 0; e < E_EXP; e++) acc[e] = 0.f;

    for (int kt = 0; kt < D_DIM / 512; kt++) {
        __syncthreads();
        for (int i = threadIdx.x; i < E_EXP * 128; i += blockDim.x) {
            int e = i >> 7, kv = i & 127;
            ((float4*)sgw[e])[kv] = ((const float4*)(gw + e * D_DIM + kt * 512))[kv];
        }
        __syncthreads();
        const float4* xr = (const float4*)(x + (size_t)n * D_DIM + kt * 512);
#pragma unroll 4
        for (int k4 = lane; k4 < 128; k4 += 32) {
            float4 xv = xr[k4];
#pragma unroll
            for (int e = 0; e < E_EXP; e++) {
                float4 wv = ((float4*)sgw[e])[k4];
                acc[e] += xv.x * wv.x + xv.y * wv.y + xv.z * wv.z + xv.w * wv.w;
            }
        }
    }
#pragma unroll
    for (int e = 0; e < E_EXP; e++)
#pragma unroll
        for (int off = 16; off; off >>= 1)
            acc[e] += __shfl_xor_sync(0xffffffffu, acc[e], off);

    if (lane == 0) {
        const int K = *topk_p;
        bool sel[E_EXP];
        int idxs[E_EXP];
#pragma unroll
        for (int e = 0; e < E_EXP; e++) sel[e] = false;
        for (int t = 0; t < K; t++) {
            int best = 0;
            float bv = -3.0e38f;
            for (int e = 0; e < E_EXP; e++)
                if (!sel[e] && acc[e] > bv) { bv = acc[e]; best = e; }
            sel[best] = true;
            idxs[t] = best;
        }
        float mx = acc[idxs[0]];
        for (int t = 1; t < K; t++) mx = fmaxf(mx, acc[idxs[t]]);
        float p[E_EXP], s = 0.f;
        for (int t = 0; t < K; t++) { p[t] = expf(acc[idxs[t]] - mx); s += p[t]; }
        float inv = 1.0f / s;
        for (int e = 0; e < E_EXP; e++) g_wfull[n * E_EXP + e] = 0.f;
        for (int t = 0; t < K; t++) g_wfull[n * E_EXP + idxs[t]] = SCALING_F * p[t] * inv;
    }
}

// ---------------- t = (x @ A^T) * w_full  -> bf16 ----------------------------
__global__ __launch_bounds__(256) void t_kernel(const float* __restrict__ x,
                                                const float* __restrict__ A) {
    __shared__ float xs[2][16][68];
    __shared__ float as[2][16][132];
    const int tx = threadIdx.x & 15, ty = threadIdx.x >> 4;
    const int bm = blockIdx.x * 64;

    const int lrow = threadIdx.x >> 2;
    const int lkv = (threadIdx.x & 3) * 4;
    const float* xg = x + (size_t)(bm + lrow) * D_DIM + lkv;
    const float* ag0 = A + (size_t)lrow * D_DIM + lkv;
    const float* ag1 = A + (size_t)(lrow + 64) * D_DIM + lkv;

    float acc[4][8];
#pragma unroll
    for (int i = 0; i < 4; i++)
#pragma unroll
        for (int j = 0; j < 8; j++) acc[i][j] = 0.f;

    float4 xv, av0, av1;
    xv = *(const float4*)(xg);
    av0 = *(const float4*)(ag0);
    av1 = *(const float4*)(ag1);
    xs[0][lkv + 0][lrow] = xv.x; xs[0][lkv + 1][lrow] = xv.y;
    xs[0][lkv + 2][lrow] = xv.z; xs[0][lkv + 3][lrow] = xv.w;
    as[0][lkv + 0][lrow] = av0.x; as[0][lkv + 1][lrow] = av0.y;
    as[0][lkv + 2][lrow] = av0.z; as[0][lkv + 3][lrow] = av0.w;
    as[0][lkv + 0][lrow + 64] = av1.x; as[0][lkv + 1][lrow + 64] = av1.y;
    as[0][lkv + 2][lrow + 64] = av1.z; as[0][lkv + 3][lrow + 64] = av1.w;
    __syncthreads();

    const int NKT = D_DIM / 16;
    for (int kt = 0; kt < NKT; kt++) {
        int buf = kt & 1;
        if (kt + 1 < NKT) {
            xv = *(const float4*)(xg + (kt + 1) * 16);
            av0 = *(const float4*)(ag0 + (kt + 1) * 16);
            av1 = *(const float4*)(ag1 + (kt + 1) * 16);
        }
#pragma unroll
        for (int kk = 0; kk < 16; kk++) {
            float4 a_ = *(const float4*)&xs[buf][kk][ty * 4];
            float4 b0 = *(const float4*)&as[buf][kk][tx * 8];
            float4 b1 = *(const float4*)&as[buf][kk][tx * 8 + 4];
            float bb[8] = {b0.x, b0.y, b0.z, b0.w, b1.x, b1.y, b1.z, b1.w};
            float aa[4] = {a_.x, a_.y, a_.z, a_.w};
#pragma unroll
            for (int i = 0; i < 4; i++)
#pragma unroll
                for (int j = 0; j < 8; j++) acc[i][j] = fmaf(aa[i], bb[j], acc[i][j]);
        }
        if (kt + 1 < NKT) {
            int nb = buf ^ 1;
            xs[nb][lkv + 0][lrow] = xv.x; xs[nb][lkv + 1][lrow] = xv.y;
            xs[nb][lkv + 2][lrow] = xv.z; xs[nb][lkv + 3][lrow] = xv.w;
            as[nb][lkv + 0][lrow] = av0.x; as[nb][lkv + 1][lrow] = av0.y;
            as[nb][lkv + 2][lrow] = av0.z; as[nb][lkv + 3][lrow] = av0.w;
            as[nb][lkv + 0][lrow + 64] = av1.x; as[nb][lkv + 1][lrow + 64] = av1.y;
            as[nb][lkv + 2][lrow + 64] = av1.z; as[nb][lkv + 3][lrow + 64] = av1.w;
        }
        __syncthreads();
    }

    const int e = tx >> 1;
#pragma unroll
    for (int i = 0; i < 4; i++) {
        int n_ = bm + ty * 4 + i;
        float w = g_wfull[n_ * E_EXP + e];
        uint4 pk;
        pk.x = pack_bf2(acc[i][0] * w, acc[i][1] * w);
        pk.y = pack_bf2(acc[i][2] * w, acc[i][3] * w);
        pk.z = pack_bf2(acc[i][4] * w, acc[i][5] * w);
        pk.w = pack_bf2(acc[i][6] * w, acc[i][7] * w);
        *(uint4*)&g_tbf[(size_t)n_ * EJ + tx * 8] = pk;
    }
}

// ---------------- main mma.sync GEMM -----------------------------------------
// y[bm:+128, bn:+128] = xhi@Whi^T + xhi@Wlo^T + xlo@Whi^T  (K=4096)
//                     + t @ BcatT^T                         (K=128, hi only)
// 256 thr (4x2 warps, 32x64 warp tile), BK=32, 2-stage pipeline, 40KB/stage
// -> 80KB/CTA -> 2 CTAs/SM: independent barriers keep the HMMA pipe fed.
#define ROWB 80
#define AHI_O 0
#define ALO_O 10240
#define BHI_O 20480
#define BLO_O 30720
#define STAGE_B 40960
#define NCH 132        // 128 main + 4 lora chunks
#define DSMEM_TOTAL (2 * STAGE_B)

__device__ __forceinline__ void load_stage(int c, int buf, int bm, int bn, uint32_t sm) {
    const uint32_t sb = sm + buf * STAGE_B;
    const int tid = threadIdx.x;
    if (c < 128) {
        const char* xh = (const char*)g_xhi;
        const char* xl = (const char*)g_xlo;
        const char* wh = (const char*)g_whi;
        const char* wl = (const char*)g_wlo;
        const size_t kofs = (size_t)c * 64;  // bytes into 8192B row
        // 2048 cp16 ops, 8 per thread: [AHI 512][ALO 512][BHI 512][BLO 512]
#pragma unroll
        for (int t = 0; t < 8; t++) {
            int idx = tid + t * 256;
            int j = idx & 511, row = j >> 2, seg = j & 3;
            int region = idx >> 9;
            uint32_t dst = sb + region * 10240 + row * ROWB + seg * 16;
            const char* src;
            if (region == 0)      src = xh + (size_t)(bm + row) * 8192 + kofs + seg * 16;
            else if (region == 1) src = xl + (size_t)(bm + row) * 8192 + kofs + seg * 16;
            else if (region == 2) src = wh + (size_t)(bn + row) * 8192 + kofs + seg * 16;
            else                  src = wl + (size_t)(bn + row) * 8192 + kofs + seg * 16;
            cp16(dst, src);
        }
    } else {
        const char* tp = (const char*)g_tbf;
        const char* bp = (const char*)g_bcatT;
        const size_t kofs = (size_t)(c - 128) * 64;  // bytes into 256B row
        // 1024 cp16 ops, 4 per thread: [AHI 512 from t][BHI 512 from bcat]
#pragma unroll
        for (int t = 0; t < 4; t++) {
            int idx = tid + t * 256;
            int j = idx & 511, row = j >> 2, seg = j & 3;
            if (idx < 512)
                cp16(sb + AHI_O + row * ROWB + seg * 16,
                     tp + (size_t)(bm + row) * 256 + kofs + seg * 16);
            else
                cp16(sb + BHI_O + row * ROWB + seg * 16,
                     bp + (size_t)(bn + row) * 256 + kofs + seg * 16);
        }
    }
    cp_commit();
}

__global__ __launch_bounds__(256, 2) void main_mma_kernel(float* __restrict__ y) {
    extern __shared__ char smem[];
    const uint32_t sm = smem_u32(smem);
    const int tid = threadIdx.x;
    const int wid = tid >> 5, lane = tid & 31;
    const int wm = wid & 3, wn = wid >> 2;          // 4x2 warp grid
    const int bm = blockIdx.y * 128, bn = blockIdx.x * 128;

    const int lrow = (lane & 7) + ((lane >> 3) & 1) * 8;
    const int lkh = (lane >> 4) * 16;

    float acc[2][8][4];
#pragma unroll
    for (int mt = 0; mt < 2; mt++)
#pragma unroll
        for (int j = 0; j < 8; j++)
#pragma unroll
            for (int q = 0; q < 4; q++) acc[mt][j][q] = 0.f;

    load_stage(0, 0, bm, bn, sm);
    load_stage(1, 1, bm, bn, sm);

    for (int c = 0; c < NCH; c++) {
        const int buf = c & 1;
        cp_wait1();          // group c complete (c+1 may still be in flight)
        __syncthreads();

        const bool lora = (c >= 128);
        const uint32_t sb = sm + buf * STAGE_B;
        const uint32_t a_base = sb + AHI_O + (wm * 32 + lrow) * ROWB + lkh;
        const uint32_t al_base = sb + ALO_O + (wm * 32 + lrow) * ROWB + lkh;
        const uint32_t b_base = sb + BHI_O + (wn * 64 + lrow) * ROWB + lkh;
        const uint32_t bl_base = sb + BLO_O + (wn * 64 + lrow) * ROWB + lkh;

#pragma unroll
        for (int s = 0; s < 2; s++) {
            const uint32_t so = s * 32;  // k16 step within BK=32 (32B)
            uint32_t ah[2][4], al[2][4], b[4][4];
#pragma unroll
            for (int mt = 0; mt < 2; mt++) ldm4(ah[mt], a_base + mt * 16 * ROWB + so);
            if (!lora)
#pragma unroll
                for (int mt = 0; mt < 2; mt++) ldm4(al[mt], al_base + mt * 16 * ROWB + so);
#pragma unroll
            for (int nt = 0; nt < 4; nt++) ldm4(b[nt], b_base + nt * 16 * ROWB + so);
            // hi*hi
#pragma unroll
            for (int mt = 0; mt < 2; mt++)
#pragma unroll
                for (int nt = 0; nt < 4; nt++) {
                    mma_bf16(acc[mt][nt * 2 + 0], ah[mt], b[nt][0], b[nt][2]);
                    mma_bf16(acc[mt][nt * 2 + 1], ah[mt], b[nt][1], b[nt][3]);
                }
            if (!lora) {
                // lo*hi
#pragma unroll
                for (int mt = 0; mt < 2; mt++)
#pragma unroll
                    for (int nt = 0; nt < 4; nt++) {
                        mma_bf16(acc[mt][nt * 2 + 0], al[mt], b[nt][0], b[nt][2]);
                        mma_bf16(acc[mt][nt * 2 + 1], al[mt], b[nt][1], b[nt][3]);
                    }
                // hi*lo: reload b from Wlo
#pragma unroll
                for (int nt = 0; nt < 4; nt++) ldm4(b[nt], bl_base + nt * 16 * ROWB + so);
#pragma unroll
                for (int mt = 0; mt < 2; mt++)
#pragma unroll
                    for (int nt = 0; nt < 4; nt++) {
                        mma_bf16(acc[mt][nt * 2 + 0], ah[mt], b[nt][0], b[nt][2]);
                        mma_bf16(acc[mt][nt * 2 + 1], ah[mt], b[nt][1], b[nt][3]);
                    }
            }
        }
        __syncthreads();     // all warps done with buf before refilling it
        if (c + 2 < NCH) load_stage(c + 2, buf, bm, bn, sm);
        else cp_commit();    // keep group accounting uniform
    }

    // ---- epilogue: fragment -> y ----
    const int r0 = bm + wm * 32 + (lane >> 2);
    const int col0 = bn + wn * 64 + (lane & 3) * 2;
#pragma unroll
    for (int mt = 0; mt < 2; mt++)
#pragma unroll
        for (int j = 0; j < 8; j++) {
            int r = r0 + mt * 16;
            int cc = col0 + j * 8;
            *(float2*)&y[(size_t)r * D_DIM + cc] = make_float2(acc[mt][j][0], acc[mt][j][1]);
            *(float2*)&y[(size_t)(r + 8) * D_DIM + cc] = make_float2(acc[mt][j][2], acc[mt][j][3]);
        }
}

// -----------------------------------------------------------------------------
extern "C" void kernel_launch(void* const* d_in, const int* in_sizes, int n_in,
                              void* d_out, int out_size) {
    const float* x = (const float*)d_in[0];
    const float* base_W = (const float*)d_in[1];
    const float* gate_W = (const float*)d_in[2];
    const float* A = (const float*)d_in[3];
    const float* B = (const float*)d_in[4];
    const int* topk = (const int*)d_in[5];
    float* y = (float*)d_out;

    cudaFuncSetAttribute(main_mma_kernel, cudaFuncAttributeMaxDynamicSharedMemorySize,
                         DSMEM_TOTAL);

    // 4 launches: main_mma_kernel stays on ncu's -s 5 profile slot.
    prep_kernel<<<2048, 256>>>(x, base_W, B);
    gate_kernel<<<N_TOK / 4, 128>>>(x, gate_W, topk);
    t_kernel<<<N_TOK / 64, 256>>>(x, A);
    main_mma_kernel<<<dim3(D_DIM / 128, N_TOK / 128), 256, DSMEM_TOTAL>>>(y);
}

// round 13
// speedup vs baseline: 2.7394x; 1.1208x over previous
#include <cuda_runtime.h>
#include <cuda_bf16.h>
#include <cstdint>

#define N_TOK 8192
#define D_DIM 4096
#define E_EXP 8
#define R_RANK 16
#define EJ (E_EXP * R_RANK)   // 128
#define SCALING_F 2.0f

// ---------------- device-global scratch (no allocation allowed) --------------
__device__ float          g_wfull[N_TOK * E_EXP];
__device__ __nv_bfloat16  g_xhi[(size_t)N_TOK * D_DIM];
__device__ __nv_bfloat16  g_xlo[(size_t)N_TOK * D_DIM];
__device__ __nv_bfloat16  g_whi[(size_t)D_DIM * D_DIM];
__device__ __nv_bfloat16  g_wlo[(size_t)D_DIM * D_DIM];
__device__ __nv_bfloat16  g_abf[(size_t)EJ * D_DIM];     // A as [j=e*16+r][D] bf16
__device__ __nv_bfloat16  g_tbf[(size_t)N_TOK * EJ];     // t in bf16 [8192][128]
__device__ __nv_bfloat16  g_bcatT[(size_t)D_DIM * EJ];   // BcatT[d][j=e*16+r]

// ---------------- helpers ----------------------------------------------------
__device__ __forceinline__ uint32_t smem_u32(const void* p) {
    uint32_t a;
    asm("{ .reg .u64 t; cvta.to.shared.u64 t, %1; cvt.u32.u64 %0, t; }" : "=r"(a) : "l"(p));
    return a;
}
__device__ __forceinline__ void cp16(uint32_t dst, const void* src) {
    asm volatile("cp.async.cg.shared.global [%0], [%1], 16;" :: "r"(dst), "l"(src));
}
__device__ __forceinline__ void cp_commit() {
    asm volatile("cp.async.commit_group;" ::: "memory");
}
__device__ __forceinline__ void cp_wait1() {
    asm volatile("cp.async.wait_group 1;" ::: "memory");
}
__device__ __forceinline__ void ldm4(uint32_t* r, uint32_t addr) {
    asm volatile("ldmatrix.sync.aligned.m8n8.x4.shared.b16 {%0,%1,%2,%3}, [%4];"
                 : "=r"(r[0]), "=r"(r[1]), "=r"(r[2]), "=r"(r[3]) : "r"(addr));
}
__device__ __forceinline__ void mma_bf16(float* c, const uint32_t* a, uint32_t b0,
                                         uint32_t b1) {
    asm volatile(
        "mma.sync.aligned.m16n8k16.row.col.f32.bf16.bf16.f32 "
        "{%0,%1,%2,%3}, {%4,%5,%6,%7}, {%8,%9}, {%0,%1,%2,%3};"
        : "+f"(c[0]), "+f"(c[1]), "+f"(c[2]), "+f"(c[3])
        : "r"(a[0]), "r"(a[1]), "r"(a[2]), "r"(a[3]), "r"(b0), "r"(b1));
}
__device__ __forceinline__ uint32_t pack_bf2(float a, float b) {
    __nv_bfloat162 t = __floats2bfloat162_rn(a, b);
    return *reinterpret_cast<uint32_t*>(&t);
}

// ---------------- prep: split x, split W, BcatT, A->bf16 (ONE kernel) --------
#define NX4 ((N_TOK * D_DIM) / 4)            // 8388608 float4 units
#define NW4 ((D_DIM * D_DIM) / 4)            // 4194304
#define NBC (D_DIM * EJ)                     // 524288
#define NA4 ((EJ * D_DIM) / 4)               // 131072
#define NPREP (NX4 + NW4 + NBC + NA4)

__device__ __forceinline__ void split4(const float* __restrict__ src,
                                       __nv_bfloat16* __restrict__ hi,
                                       __nv_bfloat16* __restrict__ lo, int i) {
    float4 v = ((const float4*)src)[i];
    __nv_bfloat16 h0 = __float2bfloat16_rn(v.x), h1 = __float2bfloat16_rn(v.y);
    __nv_bfloat16 h2 = __float2bfloat16_rn(v.z), h3 = __float2bfloat16_rn(v.w);
    uint2 ph, pl;
    {
        __nv_bfloat162 a = {h0, h1}, b = {h2, h3};
        ph.x = *reinterpret_cast<uint32_t*>(&a);
        ph.y = *reinterpret_cast<uint32_t*>(&b);
    }
    pl.x = pack_bf2(v.x - __bfloat162float(h0), v.y - __bfloat162float(h1));
    pl.y = pack_bf2(v.z - __bfloat162float(h2), v.w - __bfloat162float(h3));
    ((uint2*)hi)[i] = ph;
    ((uint2*)lo)[i] = pl;
}

__global__ __launch_bounds__(256) void prep_kernel(const float* __restrict__ x,
                                                   const float* __restrict__ W,
                                                   const float* __restrict__ B,
                                                   const float* __restrict__ A) {
    for (int i = blockIdx.x * blockDim.x + threadIdx.x; i < NPREP;
         i += gridDim.x * blockDim.x) {
        if (i < NX4) {
            split4(x, g_xhi, g_xlo, i);
        } else if (i < NX4 + NW4) {
            split4(W, g_whi, g_wlo, i - NX4);
        } else if (i < NX4 + NW4 + NBC) {
            int j2 = i - NX4 - NW4;               // [0, 4096*128)
            int d = j2 >> 7, j = j2 & 127, e = j >> 4, r = j & 15;
            g_bcatT[(size_t)d * EJ + j] = __float2bfloat16_rn(
                B[(size_t)e * D_DIM * R_RANK + (size_t)d * R_RANK + r]);
        } else {
            int i4 = i - NX4 - NW4 - NBC;         // A flat is already [j][d]
            float4 v = ((const float4*)A)[i4];
            uint2 p;
            p.x = pack_bf2(v.x, v.y);
            p.y = pack_bf2(v.z, v.w);
            ((uint2*)g_abf)[i4] = p;
        }
    }
}

// ---------------- gate: logits + top-k softmax -> g_wfull --------------------
__global__ __launch_bounds__(128) void gate_kernel(const float* __restrict__ x,
                                                   const float* __restrict__ gw,
                                                   const int* __restrict__ topk_p) {
    __shared__ float sgw[E_EXP][512];
    const int warp = threadIdx.x >> 5, lane = threadIdx.x & 31;
    const int n = blockIdx.x * 4 + warp;

    float acc[E_EXP];
#pragma unroll
    for (int e = 0; e < E_EXP; e++) acc[e] = 0.f;

    for (int kt = 0; kt < D_DIM / 512; kt++) {
        __syncthreads();
        for (int i = threadIdx.x; i < E_EXP * 128; i += blockDim.x) {
            int e = i >> 7, kv = i & 127;
            ((float4*)sgw[e])[kv] = ((const float4*)(gw + e * D_DIM + kt * 512))[kv];
        }
        __syncthreads();
        const float4* xr = (const float4*)(x + (size_t)n * D_DIM + kt * 512);
#pragma unroll 4
        for (int k4 = lane; k4 < 128; k4 += 32) {
            float4 xv = xr[k4];
#pragma unroll
            for (int e = 0; e < E_EXP; e++) {
                float4 wv = ((float4*)sgw[e])[k4];
                acc[e] += xv.x * wv.x + xv.y * wv.y + xv.z * wv.z + xv.w * wv.w;
            }
        }
    }
#pragma unroll
    for (int e = 0; e < E_EXP; e++)
#pragma unroll
        for (int off = 16; off; off >>= 1)
            acc[e] += __shfl_xor_sync(0xffffffffu, acc[e], off);

    if (lane == 0) {
        const int K = *topk_p;
        bool sel[E_EXP];
        int idxs[E_EXP];
#pragma unroll
        for (int e = 0; e < E_EXP; e++) sel[e] = false;
        for (int t = 0; t < K; t++) {
            int best = 0;
            float bv = -3.0e38f;
            for (int e = 0; e < E_EXP; e++)
                if (!sel[e] && acc[e] > bv) { bv = acc[e]; best = e; }
            sel[best] = true;
            idxs[t] = best;
        }
        float mx = acc[idxs[0]];
        for (int t = 1; t < K; t++) mx = fmaxf(mx, acc[idxs[t]]);
        float p[E_EXP], s = 0.f;
        for (int t = 0; t < K; t++) { p[t] = expf(acc[idxs[t]] - mx); s += p[t]; }
        float inv = 1.0f / s;
        for (int e = 0; e < E_EXP; e++) g_wfull[n * E_EXP + e] = 0.f;
        for (int t = 0; t < K; t++) g_wfull[n * E_EXP + idxs[t]] = SCALING_F * p[t] * inv;
    }
}

// ---------------- t = (xhi @ Abf^T) * wfull  via mma -> bf16 -----------------
// M=8192, N=128(=EJ), K=4096. BM=128, BN=128, BK=32, 256 thr, 4x2 warps,
// warp tile 32x64, 2-stage cp.async. Epilogue folds SCALING*w[n,e].
#define T_ROWB 80
#define T_XHI_O 0
#define T_AB_O 10240
#define T_STAGE 20480
#define T_NCH 128

__device__ __forceinline__ void t_load(int c, int buf, int bm, uint32_t sm) {
    const uint32_t sb = sm + buf * T_STAGE;
    const int tid = threadIdx.x;
    const char* xh = (const char*)g_xhi;
    const char* ab = (const char*)g_abf;
    const size_t kofs = (size_t)c * 64;  // bytes into 8192B row
#pragma unroll
    for (int t = 0; t < 4; t++) {
        int idx = tid + t * 256;
        int j = idx & 511, row = j >> 2, seg = j & 3;
        if (idx < 512)
            cp16(sb + T_XHI_O + row * T_ROWB + seg * 16,
                 xh + (size_t)(bm + row) * 8192 + kofs + seg * 16);
        else
            cp16(sb + T_AB_O + row * T_ROWB + seg * 16,
                 ab + (size_t)row * 8192 + kofs + seg * 16);
    }
    cp_commit();
}

__global__ __launch_bounds__(256, 2) void t_mma_kernel() {
    extern __shared__ char smem[];
    const uint32_t sm = smem_u32(smem);
    const int tid = threadIdx.x;
    const int wid = tid >> 5, lane = tid & 31;
    const int wm = wid & 3, wn = wid >> 2;          // 4x2 warp grid
    const int bm = blockIdx.x * 128;

    const int lrow = (lane & 7) + ((lane >> 3) & 1) * 8;
    const int lkh = (lane >> 4) * 16;

    float acc[2][8][4];
#pragma unroll
    for (int mt = 0; mt < 2; mt++)
#pragma unroll
        for (int j = 0; j < 8; j++)
#pragma unroll
            for (int q = 0; q < 4; q++) acc[mt][j][q] = 0.f;

    t_load(0, 0, bm, sm);
    t_load(1, 1, bm, sm);

    for (int c = 0; c < T_NCH; c++) {
        const int buf = c & 1;
        cp_wait1();
        __syncthreads();

        const uint32_t sb = sm + buf * T_STAGE;
        const uint32_t a_base = sb + T_XHI_O + (wm * 32 + lrow) * T_ROWB + lkh;
        const uint32_t b_base = sb + T_AB_O + (wn * 64 + lrow) * T_ROWB + lkh;

#pragma unroll
        for (int s = 0; s < 2; s++) {
            const uint32_t so = s * 32;
            uint32_t ah[2][4], b[4][4];
#pragma unroll
            for (int mt = 0; mt < 2; mt++) ldm4(ah[mt], a_base + mt * 16 * T_ROWB + so);
#pragma unroll
            for (int nt = 0; nt < 4; nt++) ldm4(b[nt], b_base + nt * 16 * T_ROWB + so);
#pragma unroll
            for (int mt = 0; mt < 2; mt++)
#pragma unroll
                for (int nt = 0; nt < 4; nt++) {
                    mma_bf16(acc[mt][nt * 2 + 0], ah[mt], b[nt][0], b[nt][2]);
                    mma_bf16(acc[mt][nt * 2 + 1], ah[mt], b[nt][1], b[nt][3]);
                }
        }
        __syncthreads();
        if (c + 2 < T_NCH) t_load(c + 2, buf, bm, sm);
        else cp_commit();
    }

    // epilogue: scale by routing weight (includes SCALING), pack bf16
    const int r0 = bm + wm * 32 + (lane >> 2);
    const int col0 = wn * 64 + (lane & 3) * 2;
#pragma unroll
    for (int mt = 0; mt < 2; mt++)
#pragma unroll
        for (int j = 0; j < 8; j++) {
            int r = r0 + mt * 16;
            int cc = col0 + j * 8;           // cc even; cc,cc+1 share expert
            int e = cc >> 4;
            float w1 = g_wfull[r * E_EXP + e];
            float w2 = g_wfull[(r + 8) * E_EXP + e];
            *(uint32_t*)&g_tbf[(size_t)r * EJ + cc] =
                pack_bf2(acc[mt][j][0] * w1, acc[mt][j][1] * w1);
            *(uint32_t*)&g_tbf[(size_t)(r + 8) * EJ + cc] =
                pack_bf2(acc[mt][j][2] * w2, acc[mt][j][3] * w2);
        }
}

// ---------------- main mma.sync GEMM (R12-identical) -------------------------
// y[bm:+128, bn:+128] = xhi@Whi^T + xhi@Wlo^T + xlo@Whi^T  (K=4096)
//                     + t @ BcatT^T                         (K=128, hi only)
// 256 thr (4x2 warps, 32x64 warp tile), BK=32, 2-stage pipeline, 40KB/stage
// -> 80KB/CTA -> 2 CTAs/SM: independent barriers keep the HMMA pipe fed.
#define ROWB 80
#define AHI_O 0
#define ALO_O 10240
#define BHI_O 20480
#define BLO_O 30720
#define STAGE_B 40960
#define NCH 132        // 128 main + 4 lora chunks
#define DSMEM_TOTAL (2 * STAGE_B)

__device__ __forceinline__ void load_stage(int c, int buf, int bm, int bn, uint32_t sm) {
    const uint32_t sb = sm + buf * STAGE_B;
    const int tid = threadIdx.x;
    if (c < 128) {
        const char* xh = (const char*)g_xhi;
        const char* xl = (const char*)g_xlo;
        const char* wh = (const char*)g_whi;
        const char* wl = (const char*)g_wlo;
        const size_t kofs = (size_t)c * 64;  // bytes into 8192B row
#pragma unroll
        for (int t = 0; t < 8; t++) {
            int idx = tid + t * 256;
            int j = idx & 511, row = j >> 2, seg = j & 3;
            int region = idx >> 9;
            uint32_t dst = sb + region * 10240 + row * ROWB + seg * 16;
            const char* src;
            if (region == 0)      src = xh + (size_t)(bm + row) * 8192 + kofs + seg * 16;
            else if (region == 1) src = xl + (size_t)(bm + row) * 8192 + kofs + seg * 16;
            else if (region == 2) src = wh + (size_t)(bn + row) * 8192 + kofs + seg * 16;
            else                  src = wl + (size_t)(bn + row) * 8192 + kofs + seg * 16;
            cp16(dst, src);
        }
    } else {
        const char* tp = (const char*)g_tbf;
        const char* bp = (const char*)g_bcatT;
        const size_t kofs = (size_t)(c - 128) * 64;  // bytes into 256B row
#pragma unroll
        for (int t = 0; t < 4; t++) {
            int idx = tid + t * 256;
            int j = idx & 511, row = j >> 2, seg = j & 3;
            if (idx < 512)
                cp16(sb + AHI_O + row * ROWB + seg * 16,
                     tp + (size_t)(bm + row) * 256 + kofs + seg * 16);
            else
                cp16(sb + BHI_O + row * ROWB + seg * 16,
                     bp + (size_t)(bn + row) * 256 + kofs + seg * 16);
        }
    }
    cp_commit();
}

__global__ __launch_bounds__(256, 2) void main_mma_kernel(float* __restrict__ y) {
    extern __shared__ char smem[];
    const uint32_t sm = smem_u32(smem);
    const int tid = threadIdx.x;
    const int wid = tid >> 5, lane = tid & 31;
    const int wm = wid & 3, wn = wid >> 2;          // 4x2 warp grid
    const int bm = blockIdx.y * 128, bn = blockIdx.x * 128;

    const int lrow = (lane & 7) + ((lane >> 3) & 1) * 8;
    const int lkh = (lane >> 4) * 16;

    float acc[2][8][4];
#pragma unroll
    for (int mt = 0; mt < 2; mt++)
#pragma unroll
        for (int j = 0; j < 8; j++)
#pragma unroll
            for (int q = 0; q < 4; q++) acc[mt][j][q] = 0.f;

    load_stage(0, 0, bm, bn, sm);
    load_stage(1, 1, bm, bn, sm);

    for (int c = 0; c < NCH; c++) {
        const int buf = c & 1;
        cp_wait1();
        __syncthreads();

        const bool lora = (c >= 128);
        const uint32_t sb = sm + buf * STAGE_B;
        const uint32_t a_base = sb + AHI_O + (wm * 32 + lrow) * ROWB + lkh;
        const uint32_t al_base = sb + ALO_O + (wm * 32 + lrow) * ROWB + lkh;
        const uint32_t b_base = sb + BHI_O + (wn * 64 + lrow) * ROWB + lkh;
        const uint32_t bl_base = sb + BLO_O + (wn * 64 + lrow) * ROWB + lkh;

#pragma unroll
        for (int s = 0; s < 2; s++) {
            const uint32_t so = s * 32;
            uint32_t ah[2][4], al[2][4], b[4][4];
#pragma unroll
            for (int mt = 0; mt < 2; mt++) ldm4(ah[mt], a_base + mt * 16 * ROWB + so);
            if (!lora)
#pragma unroll
                for (int mt = 0; mt < 2; mt++) ldm4(al[mt], al_base + mt * 16 * ROWB + so);
#pragma unroll
            for (int nt = 0; nt < 4; nt++) ldm4(b[nt], b_base + nt * 16 * ROWB + so);
            // hi*hi
#pragma unroll
            for (int mt = 0; mt < 2; mt++)
#pragma unroll
                for (int nt = 0; nt < 4; nt++) {
                    mma_bf16(acc[mt][nt * 2 + 0], ah[mt], b[nt][0], b[nt][2]);
                    mma_bf16(acc[mt][nt * 2 + 1], ah[mt], b[nt][1], b[nt][3]);
                }
            if (!lora) {
                // lo*hi
#pragma unroll
                for (int mt = 0; mt < 2; mt++)
#pragma unroll
                    for (int nt = 0; nt < 4; nt++) {
                        mma_bf16(acc[mt][nt * 2 + 0], al[mt], b[nt][0], b[nt][2]);
                        mma_bf16(acc[mt][nt * 2 + 1], al[mt], b[nt][1], b[nt][3]);
                    }
                // hi*lo: reload b from Wlo
#pragma unroll
                for (int nt = 0; nt < 4; nt++) ldm4(b[nt], bl_base + nt * 16 * ROWB + so);
#pragma unroll
                for (int mt = 0; mt < 2; mt++)
#pragma unroll
                    for (int nt = 0; nt < 4; nt++) {
                        mma_bf16(acc[mt][nt * 2 + 0], ah[mt], b[nt][0], b[nt][2]);
                        mma_bf16(acc[mt][nt * 2 + 1], ah[mt], b[nt][1], b[nt][3]);
                    }
            }
        }
        __syncthreads();
        if (c + 2 < NCH) load_stage(c + 2, buf, bm, bn, sm);
        else cp_commit();
    }

    // ---- epilogue: fragment -> y ----
    const int r0 = bm + wm * 32 + (lane >> 2);
    const int col0 = bn + wn * 64 + (lane & 3) * 2;
#pragma unroll
    for (int mt = 0; mt < 2; mt++)
#pragma unroll
        for (int j = 0; j < 8; j++) {
            int r = r0 + mt * 16;
            int cc = col0 + j * 8;
            *(float2*)&y[(size_t)r * D_DIM + cc] = make_float2(acc[mt][j][0], acc[mt][j][1]);
            *(float2*)&y[(size_t)(r + 8) * D_DIM + cc] = make_float2(acc[mt][j][2], acc[mt][j][3]);
        }
}

// -----------------------------------------------------------------------------
extern "C" void kernel_launch(void* const* d_in, const int* in_sizes, int n_in,
                              void* d_out, int out_size) {
    const float* x = (const float*)d_in[0];
    const float* base_W = (const float*)d_in[1];
    const float* gate_W = (const float*)d_in[2];
    const float* A = (const float*)d_in[3];
    const float* B = (const float*)d_in[4];
    const int* topk = (const int*)d_in[5];
    float* y = (float*)d_out;

    cudaFuncSetAttribute(main_mma_kernel, cudaFuncAttributeMaxDynamicSharedMemorySize,
                         DSMEM_TOTAL);
    cudaFuncSetAttribute(t_mma_kernel, cudaFuncAttributeMaxDynamicSharedMemorySize,
                         2 * T_STAGE);

    // 4 launches: main_mma_kernel stays on ncu's -s 5 profile slot.
    prep_kernel<<<2048, 256>>>(x, base_W, B, A);
    gate_kernel<<<N_TOK / 4, 128>>>(x, gate_W, topk);
    t_mma_kernel<<<N_TOK / 128, 256, 2 * T_STAGE>>>();
    main_mma_kernel<<<dim3(D_DIM / 128, N_TOK / 128), 256, DSMEM_TOTAL>>>(y);
}

// round 14
// speedup vs baseline: 2.8608x; 1.0443x over previous
#include <cuda_runtime.h>
#include <cuda_bf16.h>
#include <cstdint>

#define N_TOK 8192
#define D_DIM 4096
#define E_EXP 8
#define R_RANK 16
#define EJ (E_EXP * R_RANK)   // 128
#define SCALING_F 2.0f

// ---------------- device-global scratch (no allocation allowed) --------------
__device__ float          g_wfull[N_TOK * E_EXP];
__device__ __nv_bfloat16  g_xhi[(size_t)N_TOK * D_DIM];
__device__ __nv_bfloat16  g_xlo[(size_t)N_TOK * D_DIM];
__device__ __nv_bfloat16  g_whi[(size_t)D_DIM * D_DIM];
__device__ __nv_bfloat16  g_wlo[(size_t)D_DIM * D_DIM];
__device__ __nv_bfloat16  g_abf[(size_t)EJ * D_DIM];     // A as [j=e*16+r][D] bf16
__device__ __nv_bfloat16  g_tbf[(size_t)N_TOK * EJ];     // t in bf16 [8192][128]
__device__ __nv_bfloat16  g_bcatT[(size_t)D_DIM * EJ];   // BcatT[d][j=e*16+r]

// ---------------- helpers ----------------------------------------------------
__device__ __forceinline__ uint32_t smem_u32(const void* p) {
    uint32_t a;
    asm("{ .reg .u64 t; cvta.to.shared.u64 t, %1; cvt.u32.u64 %0, t; }" : "=r"(a) : "l"(p));
    return a;
}
__device__ __forceinline__ void cp16(uint32_t dst, const void* src) {
    asm volatile("cp.async.cg.shared.global [%0], [%1], 16;" :: "r"(dst), "l"(src));
}
__device__ __forceinline__ void cp_commit() {
    asm volatile("cp.async.commit_group;" ::: "memory");
}
__device__ __forceinline__ void cp_wait1() {
    asm volatile("cp.async.wait_group 1;" ::: "memory");
}
__device__ __forceinline__ void ldm4(uint32_t* r, uint32_t addr) {
    asm volatile("ldmatrix.sync.aligned.m8n8.x4.shared.b16 {%0,%1,%2,%3}, [%4];"
                 : "=r"(r[0]), "=r"(r[1]), "=r"(r[2]), "=r"(r[3]) : "r"(addr));
}
__device__ __forceinline__ void mma_bf16(float* c, const uint32_t* a, uint32_t b0,
                                         uint32_t b1) {
    asm volatile(
        "mma.sync.aligned.m16n8k16.row.col.f32.bf16.bf16.f32 "
        "{%0,%1,%2,%3}, {%4,%5,%6,%7}, {%8,%9}, {%0,%1,%2,%3};"
        : "+f"(c[0]), "+f"(c[1]), "+f"(c[2]), "+f"(c[3])
        : "r"(a[0]), "r"(a[1]), "r"(a[2]), "r"(a[3]), "r"(b0), "r"(b1));
}
__device__ __forceinline__ uint32_t pack_bf2(float a, float b) {
    __nv_bfloat162 t = __floats2bfloat162_rn(a, b);
    return *reinterpret_cast<uint32_t*>(&t);
}

// ---------------- prep: split x, split W, BcatT, A->bf16 (ONE kernel) --------
#define NX4 ((N_TOK * D_DIM) / 4)            // 8388608 float4 units
#define NW4 ((D_DIM * D_DIM) / 4)            // 4194304
#define NBC (D_DIM * EJ)                     // 524288
#define NA4 ((EJ * D_DIM) / 4)               // 131072
#define NPREP (NX4 + NW4 + NBC + NA4)

__device__ __forceinline__ void split4(const float* __restrict__ src,
                                       __nv_bfloat16* __restrict__ hi,
                                       __nv_bfloat16* __restrict__ lo, int i) {
    float4 v = ((const float4*)src)[i];
    __nv_bfloat16 h0 = __float2bfloat16_rn(v.x), h1 = __float2bfloat16_rn(v.y);
    __nv_bfloat16 h2 = __float2bfloat16_rn(v.z), h3 = __float2bfloat16_rn(v.w);
    uint2 ph, pl;
    {
        __nv_bfloat162 a = {h0, h1}, b = {h2, h3};
        ph.x = *reinterpret_cast<uint32_t*>(&a);
        ph.y = *reinterpret_cast<uint32_t*>(&b);
    }
    pl.x = pack_bf2(v.x - __bfloat162float(h0), v.y - __bfloat162float(h1));
    pl.y = pack_bf2(v.z - __bfloat162float(h2), v.w - __bfloat162float(h3));
    ((uint2*)hi)[i] = ph;
    ((uint2*)lo)[i] = pl;
}

__global__ __launch_bounds__(256) void prep_kernel(const float* __restrict__ x,
                                                   const float* __restrict__ W,
                                                   const float* __restrict__ B,
                                                   const float* __restrict__ A) {
    for (int i = blockIdx.x * blockDim.x + threadIdx.x; i < NPREP;
         i += gridDim.x * blockDim.x) {
        if (i < NX4) {
            split4(x, g_xhi, g_xlo, i);
        } else if (i < NX4 + NW4) {
            split4(W, g_whi, g_wlo, i - NX4);
        } else if (i < NX4 + NW4 + NBC) {
            int j2 = i - NX4 - NW4;               // [0, 4096*128)
            int d = j2 >> 7, j = j2 & 127, e = j >> 4, r = j & 15;
            g_bcatT[(size_t)d * EJ + j] = __float2bfloat16_rn(
                B[(size_t)e * D_DIM * R_RANK + (size_t)d * R_RANK + r]);
        } else {
            int i4 = i - NX4 - NW4 - NBC;         // A flat is already [j][d]
            float4 v = ((const float4*)A)[i4];
            uint2 p;
            p.x = pack_bf2(v.x, v.y);
            p.y = pack_bf2(v.z, v.w);
            ((uint2*)g_abf)[i4] = p;
        }
    }
}

// ---------------- gate: logits + top-k softmax -> g_wfull --------------------
__global__ __launch_bounds__(128) void gate_kernel(const float* __restrict__ x,
                                                   const float* __restrict__ gw,
                                                   const int* __restrict__ topk_p) {
    __shared__ float sgw[E_EXP][512];
    const int warp = threadIdx.x >> 5, lane = threadIdx.x & 31;
    const int n = blockIdx.x * 4 + warp;

    float acc[E_EXP];
#pragma unroll
    for (int e = 0; e < E_EXP; e++) acc[e] = 0.f;

    for (int kt = 0; kt < D_DIM / 512; kt++) {
        __syncthreads();
        for (int i = threadIdx.x; i < E_EXP * 128; i += blockDim.x) {
            int e = i >> 7, kv = i & 127;
            ((float4*)sgw[e])[kv] = ((const float4*)(gw + e * D_DIM + kt * 512))[kv];
        }
        __syncthreads();
        const float4* xr = (const float4*)(x + (size_t)n * D_DIM + kt * 512);
#pragma unroll 4
        for (int k4 = lane; k4 < 128; k4 += 32) {
            float4 xv = xr[k4];
#pragma unroll
            for (int e = 0; e < E_EXP; e++) {
                float4 wv = ((float4*)sgw[e])[k4];
                acc[e] += xv.x * wv.x + xv.y * wv.y + xv.z * wv.z + xv.w * wv.w;
            }
        }
    }
#pragma unroll
    for (int e = 0; e < E_EXP; e++)
#pragma unroll
        for (int off = 16; off; off >>= 1)
            acc[e] += __shfl_xor_sync(0xffffffffu, acc[e], off);

    if (lane == 0) {
        const int K = *topk_p;
        bool sel[E_EXP];
        int idxs[E_EXP];
#pragma unroll
        for (int e = 0; e < E_EXP; e++) sel[e] = false;
        for (int t = 0; t < K; t++) {
            int best = 0;
            float bv = -3.0e38f;
            for (int e = 0; e < E_EXP; e++)
                if (!sel[e] && acc[e] > bv) { bv = acc[e]; best = e; }
            sel[best] = true;
            idxs[t] = best;
        }
        float mx = acc[idxs[0]];
        for (int t = 1; t < K; t++) mx = fmaxf(mx, acc[idxs[t]]);
        float p[E_EXP], s = 0.f;
        for (int t = 0; t < K; t++) { p[t] = expf(acc[idxs[t]] - mx); s += p[t]; }
        float inv = 1.0f / s;
        for (int e = 0; e < E_EXP; e++) g_wfull[n * E_EXP + e] = 0.f;
        for (int t = 0; t < K; t++) g_wfull[n * E_EXP + idxs[t]] = SCALING_F * p[t] * inv;
    }
}

// ---------------- t = (xhi @ Abf^T) * wfull  via mma -> bf16 (R13) -----------
#define T_ROWB 80
#define T_XHI_O 0
#define T_AB_O 10240
#define T_STAGE 20480
#define T_NCH 128

__device__ __forceinline__ void t_load(int c, int buf, int bm, uint32_t sm) {
    const uint32_t sb = sm + buf * T_STAGE;
    const int tid = threadIdx.x;
    const char* xh = (const char*)g_xhi;
    const char* ab = (const char*)g_abf;
    const size_t kofs = (size_t)c * 64;  // bytes into 8192B row
#pragma unroll
    for (int t = 0; t < 4; t++) {
        int idx = tid + t * 256;
        int j = idx & 511, row = j >> 2, seg = j & 3;
        if (idx < 512)
            cp16(sb + T_XHI_O + row * T_ROWB + seg * 16,
                 xh + (size_t)(bm + row) * 8192 + kofs + seg * 16);
        else
            cp16(sb + T_AB_O + row * T_ROWB + seg * 16,
                 ab + (size_t)row * 8192 + kofs + seg * 16);
    }
    cp_commit();
}

__global__ __launch_bounds__(256, 2) void t_mma_kernel() {
    extern __shared__ char smem[];
    const uint32_t sm = smem_u32(smem);
    const int tid = threadIdx.x;
    const int wid = tid >> 5, lane = tid & 31;
    const int wm = wid & 3, wn = wid >> 2;          // 4x2 warp grid
    const int bm = blockIdx.x * 128;

    const int lrow = (lane & 7) + ((lane >> 3) & 1) * 8;
    const int lkh = (lane >> 4) * 16;

    float acc[2][8][4];
#pragma unroll
    for (int mt = 0; mt < 2; mt++)
#pragma unroll
        for (int j = 0; j < 8; j++)
#pragma unroll
            for (int q = 0; q < 4; q++) acc[mt][j][q] = 0.f;

    t_load(0, 0, bm, sm);
    t_load(1, 1, bm, sm);

    for (int c = 0; c < T_NCH; c++) {
        const int buf = c & 1;
        cp_wait1();
        __syncthreads();

        const uint32_t sb = sm + buf * T_STAGE;
        const uint32_t a_base = sb + T_XHI_O + (wm * 32 + lrow) * T_ROWB + lkh;
        const uint32_t b_base = sb + T_AB_O + (wn * 64 + lrow) * T_ROWB + lkh;

#pragma unroll
        for (int s = 0; s < 2; s++) {
            const uint32_t so = s * 32;
            uint32_t ah[2][4], b[4][4];
#pragma unroll
            for (int mt = 0; mt < 2; mt++) ldm4(ah[mt], a_base + mt * 16 * T_ROWB + so);
#pragma unroll
            for (int nt = 0; nt < 4; nt++) ldm4(b[nt], b_base + nt * 16 * T_ROWB + so);
#pragma unroll
            for (int mt = 0; mt < 2; mt++)
#pragma unroll
                for (int nt = 0; nt < 4; nt++) {
                    mma_bf16(acc[mt][nt * 2 + 0], ah[mt], b[nt][0], b[nt][2]);
                    mma_bf16(acc[mt][nt * 2 + 1], ah[mt], b[nt][1], b[nt][3]);
                }
        }
        __syncthreads();
        if (c + 2 < T_NCH) t_load(c + 2, buf, bm, sm);
        else cp_commit();
    }

    // epilogue: scale by routing weight (includes SCALING), pack bf16
    const int r0 = bm + wm * 32 + (lane >> 2);
    const int col0 = wn * 64 + (lane & 3) * 2;
#pragma unroll
    for (int mt = 0; mt < 2; mt++)
#pragma unroll
        for (int j = 0; j < 8; j++) {
            int r = r0 + mt * 16;
            int cc = col0 + j * 8;           // cc even; cc,cc+1 share expert
            int e = cc >> 4;
            float w1 = g_wfull[r * E_EXP + e];
            float w2 = g_wfull[(r + 8) * E_EXP + e];
            *(uint32_t*)&g_tbf[(size_t)r * EJ + cc] =
                pack_bf2(acc[mt][j][0] * w1, acc[mt][j][1] * w1);
            *(uint32_t*)&g_tbf[(size_t)(r + 8) * EJ + cc] =
                pack_bf2(acc[mt][j][2] * w2, acc[mt][j][3] * w2);
        }
}

// ---------------- main mma.sync GEMM -----------------------------------------
// y[bm:+128, bn:+128] = xhi@Whi^T + xhi@Wlo^T + xlo@Whi^T  (K=4096)
//                     + t @ BcatT^T                         (K=128, hi only)
// 256 thr (4x2 warps, 32x64 warp tile), BK=32.
// NEW: exact 64B rows + XOR swizzle (chunk_phys = chunk_log ^ ((row>>1)&3))
// -> stage 32KB -> 3-stage pipeline at 2 CTAs/SM (192KB), ONE barrier/chunk.
#define ROWB 64
#define AHI_O 0
#define ALO_O 8192
#define BHI_O 16384
#define BLO_O 24576
#define STAGE_B 32768
#define NCH 132        // 128 main + 4 lora chunks
#define DSMEM_TOTAL (3 * STAGE_B)

__device__ __forceinline__ void load_stage(int c, int buf, int bm, int bn, uint32_t sm) {
    const uint32_t sb = sm + buf * STAGE_B;
    const int tid = threadIdx.x;
    if (c < 128) {
        const char* xh = (const char*)g_xhi;
        const char* xl = (const char*)g_xlo;
        const char* wh = (const char*)g_whi;
        const char* wl = (const char*)g_wlo;
        const size_t kofs = (size_t)c * 64;  // bytes into 8192B row
#pragma unroll
        for (int t = 0; t < 8; t++) {
            int idx = tid + t * 256;
            int j = idx & 511, row = j >> 2, seg = j & 3;
            int region = idx >> 9;
            int segp = seg ^ ((row >> 1) & 3);  // XOR swizzle
            uint32_t dst = sb + region * 8192 + row * ROWB + segp * 16;
            const char* src;
            if (region == 0)      src = xh + (size_t)(bm + row) * 8192 + kofs + seg * 16;
            else if (region == 1) src = xl + (size_t)(bm + row) * 8192 + kofs + seg * 16;
            else if (region == 2) src = wh + (size_t)(bn + row) * 8192 + kofs + seg * 16;
            else                  src = wl + (size_t)(bn + row) * 8192 + kofs + seg * 16;
            cp16(dst, src);
        }
    } else {
        const char* tp = (const char*)g_tbf;
        const char* bp = (const char*)g_bcatT;
        const size_t kofs = (size_t)(c - 128) * 64;  // bytes into 256B row
#pragma unroll
        for (int t = 0; t < 4; t++) {
            int idx = tid + t * 256;
            int j = idx & 511, row = j >> 2, seg = j & 3;
            int segp = seg ^ ((row >> 1) & 3);
            if (idx < 512)
                cp16(sb + AHI_O + row * ROWB + segp * 16,
                     tp + (size_t)(bm + row) * 256 + kofs + seg * 16);
            else
                cp16(sb + BHI_O + row * ROWB + segp * 16,
                     bp + (size_t)(bn + row) * 256 + kofs + seg * 16);
        }
    }
    cp_commit();
}

__global__ __launch_bounds__(256, 2) void main_mma_kernel(float* __restrict__ y) {
    extern __shared__ char smem[];
    const uint32_t sm = smem_u32(smem);
    const int tid = threadIdx.x;
    const int wid = tid >> 5, lane = tid & 31;
    const int wm = wid & 3, wn = wid >> 2;          // 4x2 warp grid
    const int bm = blockIdx.y * 128, bn = blockIdx.x * 128;

    const int lrow = (lane & 7) + ((lane >> 3) & 1) * 8;
    const int lk = lane >> 4;                        // logical 16B chunk (0/1)
    const int sw = (lrow >> 1) & 3;                  // per-lane swizzle key

    float acc[2][8][4];
#pragma unroll
    for (int mt = 0; mt < 2; mt++)
#pragma unroll
        for (int j = 0; j < 8; j++)
#pragma unroll
            for (int q = 0; q < 4; q++) acc[mt][j][q] = 0.f;

    load_stage(0, 0, bm, bn, sm);
    load_stage(1, 1, bm, bn, sm);

    for (int c = 0; c < NCH; c++) {
        const int buf = c % 3;
        cp_wait1();          // group c complete (c+1 may be in flight)
        __syncthreads();     // (a) group-c visible to all; (b) compute(c-1) done
        // safe now: buffer (c+2)%3 == (c-1)%3 was last used by compute(c-1)
        if (c + 2 < NCH) load_stage(c + 2, (c + 2) % 3, bm, bn, sm);
        else cp_commit();    // keep group accounting uniform

        const bool lora = (c >= 128);
        const uint32_t sb = sm + buf * STAGE_B;
        const uint32_t a_row = sb + AHI_O + (wm * 32 + lrow) * ROWB;
        const uint32_t al_row = sb + ALO_O + (wm * 32 + lrow) * ROWB;
        const uint32_t b_row = sb + BHI_O + (wn * 64 + lrow) * ROWB;
        const uint32_t bl_row = sb + BLO_O + (wn * 64 + lrow) * ROWB;

#pragma unroll
        for (int s = 0; s < 2; s++) {
            const uint32_t co = (uint32_t)((((s << 1) | lk) ^ sw) * 16);
            uint32_t ah[2][4], al[2][4], b[4][4];
#pragma unroll
            for (int mt = 0; mt < 2; mt++) ldm4(ah[mt], a_row + mt * 16 * ROWB + co);
            if (!lora)
#pragma unroll
                for (int mt = 0; mt < 2; mt++) ldm4(al[mt], al_row + mt * 16 * ROWB + co);
#pragma unroll
            for (int nt = 0; nt < 4; nt++) ldm4(b[nt], b_row + nt * 16 * ROWB + co);
            // hi*hi
#pragma unroll
            for (int mt = 0; mt < 2; mt++)
#pragma unroll
                for (int nt = 0; nt < 4; nt++) {
                    mma_bf16(acc[mt][nt * 2 + 0], ah[mt], b[nt][0], b[nt][2]);
                    mma_bf16(acc[mt][nt * 2 + 1], ah[mt], b[nt][1], b[nt][3]);
                }
            if (!lora) {
                // lo*hi
#pragma unroll
                for (int mt = 0; mt < 2; mt++)
#pragma unroll
                    for (int nt = 0; nt < 4; nt++) {
                        mma_bf16(acc[mt][nt * 2 + 0], al[mt], b[nt][0], b[nt][2]);
                        mma_bf16(acc[mt][nt * 2 + 1], al[mt], b[nt][1], b[nt][3]);
                    }
                // hi*lo: reload b from Wlo
#pragma unroll
                for (int nt = 0; nt < 4; nt++) ldm4(b[nt], bl_row + nt * 16 * ROWB + co);
#pragma unroll
                for (int mt = 0; mt < 2; mt++)
#pragma unroll
                    for (int nt = 0; nt < 4; nt++) {
                        mma_bf16(acc[mt][nt * 2 + 0], ah[mt], b[nt][0], b[nt][2]);
                        mma_bf16(acc[mt][nt * 2 + 1], ah[mt], b[nt][1], b[nt][3]);
                    }
            }
        }
        // no trailing barrier: next iter's top-of-loop sync provides ordering
    }

    // ---- epilogue: fragment -> y ----
    const int r0 = bm + wm * 32 + (lane >> 2);
    const int col0 = bn + wn * 64 + (lane & 3) * 2;
#pragma unroll
    for (int mt = 0; mt < 2; mt++)
#pragma unroll
        for (int j = 0; j < 8; j++) {
            int r = r0 + mt * 16;
            int cc = col0 + j * 8;
            *(float2*)&y[(size_t)r * D_DIM + cc] = make_float2(acc[mt][j][0], acc[mt][j][1]);
            *(float2*)&y[(size_t)(r + 8) * D_DIM + cc] = make_float2(acc[mt][j][2], acc[mt][j][3]);
        }
}

// -----------------------------------------------------------------------------
extern "C" void kernel_launch(void* const* d_in, const int* in_sizes, int n_in,
                              void* d_out, int out_size) {
    const float* x = (const float*)d_in[0];
    const float* base_W = (const float*)d_in[1];
    const float* gate_W = (const float*)d_in[2];
    const float* A = (const float*)d_in[3];
    const float* B = (const float*)d_in[4];
    const int* topk = (const int*)d_in[5];
    float* y = (float*)d_out;

    cudaFuncSetAttribute(main_mma_kernel, cudaFuncAttributeMaxDynamicSharedMemorySize,
                         DSMEM_TOTAL);
    cudaFuncSetAttribute(t_mma_kernel, cudaFuncAttributeMaxDynamicSharedMemorySize,
                         2 * T_STAGE);

    // 4 launches: main_mma_kernel stays on ncu's -s 5 profile slot.
    prep_kernel<<<2048, 256>>>(x, base_W, B, A);
    gate_kernel<<<N_TOK / 4, 128>>>(x, gate_W, topk);
    t_mma_kernel<<<N_TOK / 128, 256, 2 * T_STAGE>>>();
    main_mma_kernel<<<dim3(D_DIM / 128, N_TOK / 128), 256, DSMEM_TOTAL>>>(y);
}